// round 9
// baseline (speedup 1.0000x reference)
#include <cuda_runtime.h>
#include <cuda_bf16.h>
#include <math.h>
#include <stdint.h>

#define Bsz 512
#define Tt  256
#define Ii  256
#define Hh  512
#define Gg  2048   // 4H
#define NCTA 128   // persistent scan grid

// ---------------- scratch (device globals; no allocation allowed) ----------
__device__ __align__(256) float g_xg[(size_t)Bsz * Tt * Gg];   // 1.07 GB
__device__ __align__(256) float g_hs[(size_t)Bsz * Tt * Hh];   // 256 MB
__device__ __align__(256) __nv_bfloat16 g_x_hi[(size_t)Bsz * Tt * Ii];
__device__ __align__(256) __nv_bfloat16 g_x_lo[(size_t)Bsz * Tt * Ii];
__device__ __align__(256) __nv_bfloat16 g_wih_hi[Ii * Gg];   // transposed [256][2048]
__device__ __align__(256) __nv_bfloat16 g_wih_lo[Ii * Gg];
// int8 quantized Whh (Q = 128*Q1 + Q0, centered Q0 in [-64,64]), plain [2048][512]
__device__ __align__(256) char g_w1[Gg * Hh];
__device__ __align__(256) char g_w0[Gg * Hh];
// int8 quantized h, double-buffered: Hq = round(h*16256) = 128*H1 + H0 (H0 centered)
__device__ __align__(256) char g_h1a[Bsz * Hh];
__device__ __align__(256) char g_h0a[Bsz * Hh];
__device__ __align__(256) char g_h1b[Bsz * Hh];
__device__ __align__(256) char g_h0b[Bsz * Hh];
__device__ unsigned g_bar;

// quantization constants: s_w = 1/sqrt(512), scale 16256 = 127*128
#define SW_D 0.04419417382415922
#define QSCALE 16256.0
#define QW_SCALE ((float)(QSCALE / SW_D))                       // w -> Wq
#define C_HI ((float)(SW_D * 16384.0 / (QSCALE * QSCALE)))      // weight of S11
#define C_LO ((float)(SW_D * 128.0   / (QSCALE * QSCALE)))      // weight of S10+S01

// ---------------- PTX helpers ----------------------------------------------
__device__ __forceinline__ uint32_t smem_u32(const void* p) {
    return (uint32_t)__cvta_generic_to_shared(p);
}
__device__ __forceinline__ void ldsm4(uint32_t* r, uint32_t addr) {
    asm volatile("ldmatrix.sync.aligned.m8n8.x4.shared.b16 {%0,%1,%2,%3},[%4];\n"
                 : "=r"(r[0]), "=r"(r[1]), "=r"(r[2]), "=r"(r[3]) : "r"(addr));
}
__device__ __forceinline__ void ldsm4t(uint32_t& r0, uint32_t& r1, uint32_t& r2, uint32_t& r3,
                                       uint32_t addr) {
    asm volatile("ldmatrix.sync.aligned.m8n8.x4.trans.shared.b16 {%0,%1,%2,%3},[%4];\n"
                 : "=r"(r0), "=r"(r1), "=r"(r2), "=r"(r3) : "r"(addr));
}
__device__ __forceinline__ void mma_bf16(float* c, const uint32_t* a, const uint32_t* b) {
    asm volatile("mma.sync.aligned.m16n8k16.row.col.f32.bf16.bf16.f32 "
                 "{%0,%1,%2,%3},{%4,%5,%6,%7},{%8,%9},{%0,%1,%2,%3};\n"
                 : "+f"(c[0]), "+f"(c[1]), "+f"(c[2]), "+f"(c[3])
                 : "r"(a[0]), "r"(a[1]), "r"(a[2]), "r"(a[3]), "r"(b[0]), "r"(b[1]));
}
__device__ __forceinline__ void mma_s8(int* c, const uint32_t* a, const uint32_t* b) {
    asm volatile("mma.sync.aligned.m16n8k32.row.col.s32.s8.s8.s32 "
                 "{%0,%1,%2,%3},{%4,%5,%6,%7},{%8,%9},{%0,%1,%2,%3};\n"
                 : "+r"(c[0]), "+r"(c[1]), "+r"(c[2]), "+r"(c[3])
                 : "r"(a[0]), "r"(a[1]), "r"(a[2]), "r"(a[3]), "r"(b[0]), "r"(b[1]));
}
__device__ __forceinline__ void cpasync16(uint32_t dst, const void* src) {
    asm volatile("cp.async.cg.shared.global [%0],[%1],16;\n" :: "r"(dst), "l"(src));
}
#define CP_COMMIT() asm volatile("cp.async.commit_group;\n" ::: "memory")
#define CP_WAIT(n)  asm volatile("cp.async.wait_group %0;\n" :: "n"(n) : "memory")

__device__ __forceinline__ float fast_sigmoid(float x) {
    return __fdividef(1.f, 1.f + __expf(-x));
}
__device__ __forceinline__ float fast_tanh(float x) {
    return 1.f - __fdividef(2.f, __expf(2.f * x) + 1.f);
}

// ---------------- prep kernels ---------------------------------------------
__global__ void conv_w_kernel(const float* __restrict__ src,
                              __nv_bfloat16* __restrict__ dhi,
                              __nv_bfloat16* __restrict__ dlo, int N, int K) {
    int idx = blockIdx.x * 256 + threadIdx.x;
    if (idx >= N * K) return;
    int n = idx / K, k = idx - n * K;
    float v = src[idx];
    __nv_bfloat16 h = __float2bfloat16(v);
    dhi[(size_t)k * Gg + n] = h;
    dlo[(size_t)k * Gg + n] = __float2bfloat16(v - __bfloat162float(h));
}

__global__ void conv_x_kernel(const float* __restrict__ src,
                              __nv_bfloat16* __restrict__ dhi,
                              __nv_bfloat16* __restrict__ dlo, int n) {
    int idx = blockIdx.x * 256 + threadIdx.x;
    if (idx >= n) return;
    float v = src[idx];
    __nv_bfloat16 h = __float2bfloat16(v);
    dhi[idx] = h;
    dlo[idx] = __float2bfloat16(v - __bfloat162float(h));
}

// Whh fp32 -> int8 hi/lo fixed point (centered low part)
__global__ void conv_whh_q_kernel(const float* __restrict__ src,
                                  char* __restrict__ w1, char* __restrict__ w0) {
    int idx = blockIdx.x * 256 + threadIdx.x;
    if (idx >= Gg * Hh) return;
    int q = __float2int_rn(src[idx] * QW_SCALE);          // |q| <= 16256
    int hi = __float2int_rn((float)q * 0.0078125f);       // round(q/128) in [-127,127]
    w1[idx] = (char)hi;
    w0[idx] = (char)(q - (hi << 7));                      // centered in [-64,64]
}

__global__ void init_kernel(char* h1a, char* h0a, char* h1b, char* h0b) {
    int i = blockIdx.x * 256 + threadIdx.x;
    if (i == 0) g_bar = 0u;
    if (i < Bsz * Hh) { h1a[i] = 0; h0a[i] = 0; h1b[i] = 0; h0b[i] = 0; }
}

// ---------------- xg GEMM (HMMA bf16x3, unchanged) --------------------------
__global__ void __launch_bounds__(256) xg_gemm_kernel(
    const __nv_bfloat16* __restrict__ Ahi, const __nv_bfloat16* __restrict__ Alo,
    const __nv_bfloat16* __restrict__ Bhi, const __nv_bfloat16* __restrict__ Blo,
    const float* __restrict__ bih, const float* __restrict__ bhh,
    float* __restrict__ C)
{
    __shared__ __align__(16) __nv_bfloat16 sA[2][128][40];
    __shared__ __align__(16) __nv_bfloat16 sB[2][32][136];
    const int tid = threadIdx.x;
    const int l = tid & 31, w = tid >> 5;
    const int wm = w >> 1, wn = w & 1;
    const int n0 = blockIdx.x * 128;
    const int m0 = blockIdx.y * 128;

    float acc[2][8][4];
#pragma unroll
    for (int mi = 0; mi < 2; mi++)
#pragma unroll
        for (int nt = 0; nt < 8; nt++)
#pragma unroll
            for (int q = 0; q < 4; q++) acc[mi][nt][q] = 0.f;

    for (int k0 = 0; k0 < Ii; k0 += 32) {
        for (int s = tid; s < 512; s += 256) {
            int row = s >> 2, ch = (s & 3) * 8;
            *(uint4*)&sA[0][row][ch] = *(const uint4*)(Ahi + (size_t)(m0 + row) * Ii + k0 + ch);
            *(uint4*)&sA[1][row][ch] = *(const uint4*)(Alo + (size_t)(m0 + row) * Ii + k0 + ch);
        }
        for (int s = tid; s < 512; s += 256) {
            int kr = s >> 4, ch = (s & 15) * 8;
            *(uint4*)&sB[0][kr][ch] = *(const uint4*)(Bhi + (size_t)(k0 + kr) * Gg + n0 + ch);
            *(uint4*)&sB[1][kr][ch] = *(const uint4*)(Blo + (size_t)(k0 + kr) * Gg + n0 + ch);
        }
        __syncthreads();
#pragma unroll
        for (int kk = 0; kk < 32; kk += 16) {
            uint32_t af[2][2][4];
#pragma unroll
            for (int p = 0; p < 2; p++)
#pragma unroll
                for (int mi = 0; mi < 2; mi++) {
                    uint32_t addr = smem_u32(
                        &sA[p][wm * 32 + mi * 16 + (l & 15)][kk + (l >> 4) * 8]);
                    ldsm4(af[p][mi], addr);
                }
            uint32_t bfr[2][8][2];
            const int krow = (l & 15);
            const int csel = (l >> 4) * 8;
#pragma unroll
            for (int p = 0; p < 2; p++)
#pragma unroll
                for (int jp = 0; jp < 4; jp++) {
                    uint32_t addr = smem_u32(&sB[p][kk + krow][wn * 64 + jp * 16 + csel]);
                    uint32_t r0, r1, r2, r3;
                    ldsm4t(r0, r1, r2, r3, addr);
                    bfr[p][jp * 2][0] = r0; bfr[p][jp * 2][1] = r1;
                    bfr[p][jp * 2 + 1][0] = r2; bfr[p][jp * 2 + 1][1] = r3;
                }
#pragma unroll
            for (int mi = 0; mi < 2; mi++)
#pragma unroll
                for (int nt = 0; nt < 8; nt++) {
                    mma_bf16(acc[mi][nt], af[0][mi], bfr[0][nt]);
                    mma_bf16(acc[mi][nt], af[0][mi], bfr[1][nt]);
                    mma_bf16(acc[mi][nt], af[1][mi], bfr[0][nt]);
                }
        }
        __syncthreads();
    }

    const int r = l >> 2, cq = (l & 3) * 2;
#pragma unroll
    for (int mi = 0; mi < 2; mi++)
#pragma unroll
        for (int nt = 0; nt < 8; nt++) {
            const int col = n0 + wn * 64 + nt * 8 + cq;
            float bs0 = bih[col] + bhh[col];
            float bs1 = bih[col + 1] + bhh[col + 1];
#pragma unroll
            for (int rr = 0; rr < 2; rr++) {
                int m = m0 + wm * 32 + mi * 16 + r + rr * 8;
                float2 v = make_float2(acc[mi][nt][rr * 2 + 0] + bs0,
                                       acc[mi][nt][rr * 2 + 1] + bs1);
                *(float2*)(C + (size_t)m * Gg + col) = v;
            }
        }
}

// ---------------- persistent INT8 scan --------------------------------------
#define SCB_OFF   0
#define SCB_HALF  33792        // 64*528
#define SCA_OFF   67584
#define SCA_SLOT  10240        // 128*80
#define SCAN8_SMEM 108544      // 67584 + 4*10240

__global__ void __launch_bounds__(256, 1) scan_i8_kernel(
    const char* __restrict__ w1p, const char* __restrict__ w0p,
    char* __restrict__ h1a, char* __restrict__ h0a,
    char* __restrict__ h1b, char* __restrict__ h0b,
    const float* __restrict__ xg, float* __restrict__ hs)
{
    extern __shared__ __align__(128) char sm[];
    const uint32_t smb = smem_u32(sm);
    const int tid = threadIdx.x, l = tid & 31, w = tid >> 5;
    const int bt = blockIdx.x >> 5;       // batch tile 0..3
    const int ctile = blockIdx.x & 31;    // ncol tile 0..31
    const int mb = bt * 128;
    const int hc0 = ctile * 16;

    // ---- fill resident B: sB[half][n][k], n = gate*16 + hc ----
#pragma unroll
    for (int half = 0; half < 2; half++) {
        const char* src = half ? w0p : w1p;
        char* dst = sm + SCB_OFF + half * SCB_HALF;
        for (int s = tid; s < 2048; s += 256) {
            int n = s >> 5;               // 0..63
            int kg = (s & 31) * 16;       // 0..496
            int gate = n >> 4, hc = n & 15;
            *(uint4*)(dst + n * 528 + kg) =
                *(const uint4*)(src + (size_t)(gate * Hh + hc0 + hc) * Hh + kg);
        }
    }
    __syncthreads();

    const int lrow = l & 15;
    const int lkb  = (l >> 4) * 16;
    const uint32_t aAddrBase = (uint32_t)((w * 16 + lrow) * 80 + lkb);
    const uint32_t bRowOff   = (uint32_t)(lrow * 528 + lkb);

    float c_reg[8];
#pragma unroll
    for (int q = 0; q < 8; q++) c_reg[q] = 0.f;

    const int a_ep = (l & 3) * 2;
    const int r0_ep = mb + w * 16 + (l >> 2);

    for (int t = 0; t < Tt; t++) {
        const char* rh1 = (t & 1) ? h1b : h1a;
        const char* rh0 = (t & 1) ? h0b : h0a;
        char* wh1 = (t & 1) ? h1a : h1b;
        char* wh0 = (t & 1) ? h0a : h0b;

        int accA[8][4], accB[8][4];
#pragma unroll
        for (int nf = 0; nf < 8; nf++)
#pragma unroll
            for (int q = 0; q < 4; q++) { accA[nf][q] = 0; accB[nf][q] = 0; }

        // prologue: stage chunk 0 into stage 0
#pragma unroll
        for (int i = 0; i < 4; i++) {
            int s = tid + i * 256;
            int half = s >> 9, rem = s & 511;
            int row = rem >> 2, kq = (rem & 3) * 16;
            const char* src = (half ? rh0 : rh1) + (size_t)(mb + row) * Hh + kq;
            cpasync16(smb + SCA_OFF + (uint32_t)(half * SCA_SLOT) + (uint32_t)(row * 80 + kq),
                      src);
        }
        CP_COMMIT();

        for (int c = 0; c < 8; c++) {
            CP_WAIT(0);
            __syncthreads();
            if (c < 7) {
                const int pc = c + 1;
                const uint32_t stbase = smb + SCA_OFF + (uint32_t)((pc & 1) * 2 * SCA_SLOT);
#pragma unroll
                for (int i = 0; i < 4; i++) {
                    int s = tid + i * 256;
                    int half = s >> 9, rem = s & 511;
                    int row = rem >> 2, kq = (rem & 3) * 16;
                    const char* src = (half ? rh0 : rh1)
                        + (size_t)(mb + row) * Hh + pc * 64 + kq;
                    cpasync16(stbase + (uint32_t)(half * SCA_SLOT) + (uint32_t)(row * 80 + kq),
                              src);
                }
                CP_COMMIT();
            }

            const uint32_t aHi = smb + SCA_OFF + (uint32_t)((c & 1) * 2 * SCA_SLOT) + aAddrBase;
            const uint32_t aLo = aHi + SCA_SLOT;
#pragma unroll
            for (int kf = 0; kf < 2; kf++) {
                const uint32_t kfo = (uint32_t)(kf * 32);
                uint32_t a1[4], a0[4];
                ldsm4(a1, aHi + kfo);
                ldsm4(a0, aLo + kfo);
                uint32_t b1[8][2], b0[8][2];
                const uint32_t kglob = (uint32_t)(c * 64) + kfo;
#pragma unroll
                for (int np = 0; np < 4; np++) {
                    uint32_t q[4];
                    ldsm4(q, smb + SCB_OFF + (uint32_t)(np * 16 * 528) + bRowOff + kglob);
                    b1[np * 2][0] = q[0]; b1[np * 2][1] = q[2];
                    b1[np * 2 + 1][0] = q[1]; b1[np * 2 + 1][1] = q[3];
                }
#pragma unroll
                for (int np = 0; np < 4; np++) {
                    uint32_t q[4];
                    ldsm4(q, smb + SCB_OFF + SCB_HALF + (uint32_t)(np * 16 * 528) + bRowOff + kglob);
                    b0[np * 2][0] = q[0]; b0[np * 2][1] = q[2];
                    b0[np * 2 + 1][0] = q[1]; b0[np * 2 + 1][1] = q[3];
                }
#pragma unroll
                for (int nf = 0; nf < 8; nf++) {
                    mma_s8(accA[nf], a1, b1[nf]);
                    mma_s8(accB[nf], a1, b0[nf]);
                    mma_s8(accB[nf], a0, b1[nf]);
                }
            }
        }

        // ---- gate epilogue ----
#pragma unroll
        for (int rr = 0; rr < 2; rr++) {
            const int b = r0_ep + rr * 8;
            const float* xb = xg + ((size_t)b * Tt + t) * Gg + hc0;
            float pre[4][4];
#pragma unroll
            for (int g = 0; g < 4; g++) {
                float2 f2a = *(const float2*)(xb + g * Hh + a_ep);
                float2 f2b = *(const float2*)(xb + g * Hh + a_ep + 8);
                pre[g][0] = C_HI * (float)accA[g * 2][rr * 2]
                          + C_LO * (float)accB[g * 2][rr * 2]         + f2a.x;
                pre[g][1] = C_HI * (float)accA[g * 2][rr * 2 + 1]
                          + C_LO * (float)accB[g * 2][rr * 2 + 1]     + f2a.y;
                pre[g][2] = C_HI * (float)accA[g * 2 + 1][rr * 2]
                          + C_LO * (float)accB[g * 2 + 1][rr * 2]     + f2b.x;
                pre[g][3] = C_HI * (float)accA[g * 2 + 1][rr * 2 + 1]
                          + C_LO * (float)accB[g * 2 + 1][rr * 2 + 1] + f2b.y;
            }
            float hn[4];
#pragma unroll
            for (int s = 0; s < 4; s++) {
                float ig = fast_sigmoid(pre[0][s]);
                float fg = fast_sigmoid(pre[1][s]);
                float gg = fast_tanh(pre[2][s]);
                float og = fast_sigmoid(pre[3][s]);
                float cv = fg * c_reg[rr * 4 + s] + ig * gg;
                c_reg[rr * 4 + s] = cv;
                hn[s] = og * fast_tanh(cv);
            }
            float* hrow = hs + ((size_t)b * Tt + t) * Hh + hc0;
            *(float2*)(hrow + a_ep)     = make_float2(hn[0], hn[1]);
            *(float2*)(hrow + a_ep + 8) = make_float2(hn[2], hn[3]);
            // quantize h -> int8 hi/lo (centered low part)
            int q[4], q1[4], q0[4];
#pragma unroll
            for (int s = 0; s < 4; s++) {
                q[s] = __float2int_rn(hn[s] * (float)QSCALE);
                q1[s] = __float2int_rn((float)q[s] * 0.0078125f);   // round(q/128)
                q0[s] = q[s] - (q1[s] << 7);                        // in [-64,64]
            }
            char2 p;
            p.x = (char)q1[0]; p.y = (char)q1[1];
            *(char2*)(wh1 + (size_t)b * Hh + hc0 + a_ep) = p;
            p.x = (char)q1[2]; p.y = (char)q1[3];
            *(char2*)(wh1 + (size_t)b * Hh + hc0 + a_ep + 8) = p;
            p.x = (char)q0[0]; p.y = (char)q0[1];
            *(char2*)(wh0 + (size_t)b * Hh + hc0 + a_ep) = p;
            p.x = (char)q0[2]; p.y = (char)q0[3];
            *(char2*)(wh0 + (size_t)b * Hh + hc0 + a_ep + 8) = p;
        }

        // ---- grid barrier ----
        if (t < Tt - 1) {
            __syncthreads();
            if (tid == 0) {
                __threadfence();
                atomicAdd(&g_bar, 1u);
                const unsigned target = (unsigned)NCTA * (unsigned)(t + 1);
                unsigned v;
                do {
                    asm volatile("ld.acquire.gpu.u32 %0,[%1];" : "=r"(v) : "l"(&g_bar));
                    if (v < target) __nanosleep(32);
                } while (v < target);
            }
            __syncthreads();
        }
    }
}

// ---------------- fused head: fc1 + BN1 + leaky + fc2 + BN2 + relu ---------
#define HEAD_DYN_SMEM ((512 * 32 + 512 * 33) * sizeof(float))

__global__ void __launch_bounds__(256) head_kernel(
    const float* __restrict__ fc1_w, const float* __restrict__ fc1_b,
    const float* __restrict__ fc2_w, const float* __restrict__ fc2_b,
    const float* __restrict__ bn1_g, const float* __restrict__ bn1_b,
    const float* __restrict__ bn2_g, const float* __restrict__ bn2_b,
    float* __restrict__ out)
{
    extern __shared__ float smf[];
    float* fc1t = smf;             // [512][32]
    float* sa   = smf + 512 * 32;  // [512][33]

    __shared__ float red1[8], red2[8];
    __shared__ float zbuf[Bsz];
    __shared__ float fc2s[32];
    __shared__ float stats[4];

    const int t = blockIdx.x;
    const int tid = threadIdx.x;
    const int warp = tid >> 5, lane = tid & 31;

    if (tid < 32) fc2s[tid] = fc2_w[tid];
    for (int idx = tid; idx < 32 * 512; idx += 256) {
        int o = idx >> 9, k = idx & 511;
        fc1t[k * 32 + o] = fc1_w[idx];
    }
    __syncthreads();

    const float bias_o = fc1_b[lane];
    for (int pr = 0; pr < 32; pr++) {
        const int b0 = warp * 64 + pr * 2;
        const int b1 = b0 + 1;
        const float4* r0 = (const float4*)(g_hs + ((size_t)b0 * Tt + t) * Hh);
        const float4* r1 = (const float4*)(g_hs + ((size_t)b1 * Tt + t) * Hh);
        float a0 = bias_o, a1 = bias_o;
#pragma unroll 4
        for (int k4 = 0; k4 < Hh / 4; k4++) {
            float4 v0 = r0[k4], v1 = r1[k4];
            const float* fp = fc1t + (k4 * 4) * 32 + lane;
            float wv;
            wv = fp[0];  a0 += v0.x * wv; a1 += v1.x * wv;
            wv = fp[32]; a0 += v0.y * wv; a1 += v1.y * wv;
            wv = fp[64]; a0 += v0.z * wv; a1 += v1.z * wv;
            wv = fp[96]; a0 += v0.w * wv; a1 += v1.w * wv;
        }
        sa[b0 * 33 + lane] = a0;
        sa[b1 * 33 + lane] = a1;
    }
    __syncthreads();

    float s = 0.f, ss = 0.f;
    for (int idx = tid; idx < Bsz * 32; idx += 256) {
        float v = sa[(idx >> 5) * 33 + (idx & 31)];
        s += v; ss += v * v;
    }
#pragma unroll
    for (int off = 16; off; off >>= 1) {
        s  += __shfl_down_sync(0xffffffffu, s,  off);
        ss += __shfl_down_sync(0xffffffffu, ss, off);
    }
    if (lane == 0) { red1[warp] = s; red2[warp] = ss; }
    __syncthreads();
    if (tid == 0) {
        float S = 0.f, SS = 0.f;
        for (int wv = 0; wv < 8; wv++) { S += red1[wv]; SS += red2[wv]; }
        float m = S / 16384.f;
        float v = SS / 16384.f - m * m;
        stats[0] = m;
        stats[1] = rsqrtf(v + 1e-5f);
    }
    __syncthreads();

    const float m1 = stats[0], inv1 = stats[1];
    const float g1 = bn1_g[t], be1 = bn1_b[t];
    const float f2b = fc2_b[0];

    for (int b = tid; b < Bsz; b += 256) {
        float acc = f2b;
#pragma unroll
        for (int o = 0; o < 32; o++) {
            float a = (sa[b * 33 + o] - m1) * inv1 * g1 + be1;
            a = a > 0.f ? a : 0.1f * a;
            acc += a * fc2s[o];
        }
        zbuf[b] = acc;
    }
    __syncthreads();

    float s2 = 0.f, ss2 = 0.f;
    for (int b = tid; b < Bsz; b += 256) { float v = zbuf[b]; s2 += v; ss2 += v * v; }
#pragma unroll
    for (int off = 16; off; off >>= 1) {
        s2  += __shfl_down_sync(0xffffffffu, s2,  off);
        ss2 += __shfl_down_sync(0xffffffffu, ss2, off);
    }
    if (lane == 0) { red1[warp] = s2; red2[warp] = ss2; }
    __syncthreads();
    if (tid == 0) {
        float S = 0.f, SS = 0.f;
        for (int wv = 0; wv < 8; wv++) { S += red1[wv]; SS += red2[wv]; }
        float m = S / (float)Bsz;
        float v = SS / (float)Bsz - m * m;
        stats[2] = m;
        stats[3] = rsqrtf(v + 1e-5f);
    }
    __syncthreads();

    const float m2 = stats[2], inv2 = stats[3];
    const float g2 = bn2_g[t], be2 = bn2_b[t];
    for (int b = tid; b < Bsz; b += 256) {
        float v = (zbuf[b] - m2) * inv2 * g2 + be2;
        out[(size_t)b * Tt + t] = v > 0.f ? v : 0.f;
    }
}

// ---------------- launch ----------------------------------------------------
extern "C" void kernel_launch(void* const* d_in, const int* in_sizes, int n_in,
                              void* d_out, int out_size)
{
    const float* x     = (const float*)d_in[0];
    const float* Wih   = (const float*)d_in[1];
    const float* Whh   = (const float*)d_in[2];
    const float* bih   = (const float*)d_in[3];
    const float* bhh   = (const float*)d_in[4];
    const float* fc1_w = (const float*)d_in[5];
    const float* fc1_b = (const float*)d_in[6];
    const float* fc2_w = (const float*)d_in[7];
    const float* fc2_b = (const float*)d_in[8];
    const float* bn1_g = (const float*)d_in[9];
    const float* bn1_b = (const float*)d_in[10];
    const float* bn2_g = (const float*)d_in[11];
    const float* bn2_b = (const float*)d_in[12];
    float* out = (float*)d_out;

    cudaFuncSetAttribute(head_kernel, cudaFuncAttributeMaxDynamicSharedMemorySize,
                         (int)HEAD_DYN_SMEM);
    cudaFuncSetAttribute(scan_i8_kernel, cudaFuncAttributeMaxDynamicSharedMemorySize,
                         SCAN8_SMEM);

    float *d_xg, *d_hs;
    __nv_bfloat16 *d_xhi, *d_xlo, *d_wihhi, *d_wihlo;
    char *d_w1, *d_w0, *d_h1a, *d_h0a, *d_h1b, *d_h0b;
    cudaGetSymbolAddress((void**)&d_xg,    g_xg);
    cudaGetSymbolAddress((void**)&d_hs,    g_hs);
    cudaGetSymbolAddress((void**)&d_xhi,   g_x_hi);
    cudaGetSymbolAddress((void**)&d_xlo,   g_x_lo);
    cudaGetSymbolAddress((void**)&d_wihhi, g_wih_hi);
    cudaGetSymbolAddress((void**)&d_wihlo, g_wih_lo);
    cudaGetSymbolAddress((void**)&d_w1,    g_w1);
    cudaGetSymbolAddress((void**)&d_w0,    g_w0);
    cudaGetSymbolAddress((void**)&d_h1a,   g_h1a);
    cudaGetSymbolAddress((void**)&d_h0a,   g_h0a);
    cudaGetSymbolAddress((void**)&d_h1b,   g_h1b);
    cudaGetSymbolAddress((void**)&d_h0b,   g_h0b);

    // prep
    conv_w_kernel<<<(Gg * Ii + 255) / 256, 256>>>(Wih, d_wihhi, d_wihlo, Gg, Ii);
    conv_whh_q_kernel<<<(Gg * Hh + 255) / 256, 256>>>(Whh, d_w1, d_w0);
    conv_x_kernel<<<((int)((size_t)Bsz * Tt * Ii) + 255) / 256, 256>>>(
        x, d_xhi, d_xlo, Bsz * Tt * Ii);
    init_kernel<<<(Bsz * Hh + 255) / 256, 256>>>(d_h1a, d_h0a, d_h1b, d_h0b);

    // xg = x @ Wih^T + bih + bhh
    xg_gemm_kernel<<<dim3(Gg / 128, (Bsz * Tt) / 128), 256>>>(
        d_xhi, d_xlo, d_wihhi, d_wihlo, bih, bhh, d_xg);

    // persistent INT8 scan
    scan_i8_kernel<<<NCTA, 256, SCAN8_SMEM>>>(d_w1, d_w0,
                                              d_h1a, d_h0a, d_h1b, d_h0b,
                                              d_xg, d_hs);

    // fused head
    head_kernel<<<Tt, 256, HEAD_DYN_SMEM>>>(fc1_w, fc1_b, fc2_w, fc2_b,
                                            bn1_g, bn1_b, bn2_g, bn2_b, out);
}

// round 10
// speedup vs baseline: 1.4489x; 1.4489x over previous
#include <cuda_runtime.h>
#include <cuda_bf16.h>
#include <cuda_fp16.h>
#include <math.h>
#include <stdint.h>

#define Bsz 512
#define Tt  256
#define Ii  256
#define Hh  512
#define Gg  2048   // 4H
#define NCTA 128   // persistent scan grid

// ---------------- scratch (device globals; no allocation allowed) ----------
__device__ __align__(256) float g_xg[(size_t)Bsz * Tt * Gg];   // 1.07 GB
__device__ __align__(256) float g_hs[(size_t)Bsz * Tt * Hh];   // 256 MB
__device__ __align__(256) __nv_bfloat16 g_x_hi[(size_t)Bsz * Tt * Ii];
__device__ __align__(256) __nv_bfloat16 g_x_lo[(size_t)Bsz * Tt * Ii];
__device__ __align__(256) __nv_bfloat16 g_wih_hi[Ii * Gg];   // transposed [256][2048]
__device__ __align__(256) __nv_bfloat16 g_wih_lo[Ii * Gg];
__device__ __align__(256) __half g_whh_h[Gg * Hh];           // fp16 Whh, plain [2048][512]
__device__ __align__(256) __half g_hA[Bsz * Hh];             // fp16 h, double-buffered
__device__ __align__(256) __half g_hB[Bsz * Hh];
__device__ unsigned g_bar;

// ---------------- PTX helpers ----------------------------------------------
__device__ __forceinline__ uint32_t smem_u32(const void* p) {
    return (uint32_t)__cvta_generic_to_shared(p);
}
__device__ __forceinline__ void ldsm4(uint32_t* r, uint32_t addr) {
    asm volatile("ldmatrix.sync.aligned.m8n8.x4.shared.b16 {%0,%1,%2,%3},[%4];\n"
                 : "=r"(r[0]), "=r"(r[1]), "=r"(r[2]), "=r"(r[3]) : "r"(addr));
}
__device__ __forceinline__ void ldsm4t(uint32_t& r0, uint32_t& r1, uint32_t& r2, uint32_t& r3,
                                       uint32_t addr) {
    asm volatile("ldmatrix.sync.aligned.m8n8.x4.trans.shared.b16 {%0,%1,%2,%3},[%4];\n"
                 : "=r"(r0), "=r"(r1), "=r"(r2), "=r"(r3) : "r"(addr));
}
__device__ __forceinline__ void mma_bf16(float* c, const uint32_t* a, const uint32_t* b) {
    asm volatile("mma.sync.aligned.m16n8k16.row.col.f32.bf16.bf16.f32 "
                 "{%0,%1,%2,%3},{%4,%5,%6,%7},{%8,%9},{%0,%1,%2,%3};\n"
                 : "+f"(c[0]), "+f"(c[1]), "+f"(c[2]), "+f"(c[3])
                 : "r"(a[0]), "r"(a[1]), "r"(a[2]), "r"(a[3]), "r"(b[0]), "r"(b[1]));
}
__device__ __forceinline__ void mma_f16(float* c, const uint32_t* a, const uint32_t* b) {
    asm volatile("mma.sync.aligned.m16n8k16.row.col.f32.f16.f16.f32 "
                 "{%0,%1,%2,%3},{%4,%5,%6,%7},{%8,%9},{%0,%1,%2,%3};\n"
                 : "+f"(c[0]), "+f"(c[1]), "+f"(c[2]), "+f"(c[3])
                 : "r"(a[0]), "r"(a[1]), "r"(a[2]), "r"(a[3]), "r"(b[0]), "r"(b[1]));
}
__device__ __forceinline__ void cpasync16(uint32_t dst, const void* src) {
    asm volatile("cp.async.cg.shared.global [%0],[%1],16;\n" :: "r"(dst), "l"(src));
}
#define CP_COMMIT() asm volatile("cp.async.commit_group;\n" ::: "memory")
#define CP_WAIT(n)  asm volatile("cp.async.wait_group %0;\n" :: "n"(n) : "memory")

__device__ __forceinline__ float fast_sigmoid(float x) {
    return __fdividef(1.f, 1.f + __expf(-x));
}
__device__ __forceinline__ float fast_tanh(float x) {
    return 1.f - __fdividef(2.f, __expf(2.f * x) + 1.f);
}

// ---------------- prep kernels ---------------------------------------------
// [N][K] fp32 -> transposed [K][N=2048] bf16 hi/lo (for xg GEMM's Wih)
__global__ void conv_w_kernel(const float* __restrict__ src,
                              __nv_bfloat16* __restrict__ dhi,
                              __nv_bfloat16* __restrict__ dlo, int N, int K) {
    int idx = blockIdx.x * 256 + threadIdx.x;
    if (idx >= N * K) return;
    int n = idx / K, k = idx - n * K;
    float v = src[idx];
    __nv_bfloat16 h = __float2bfloat16(v);
    dhi[(size_t)k * Gg + n] = h;
    dlo[(size_t)k * Gg + n] = __float2bfloat16(v - __bfloat162float(h));
}

__global__ void conv_x_kernel(const float* __restrict__ src,
                              __nv_bfloat16* __restrict__ dhi,
                              __nv_bfloat16* __restrict__ dlo, int n) {
    int idx = blockIdx.x * 256 + threadIdx.x;
    if (idx >= n) return;
    float v = src[idx];
    __nv_bfloat16 h = __float2bfloat16(v);
    dhi[idx] = h;
    dlo[idx] = __float2bfloat16(v - __bfloat162float(h));
}

// Whh fp32 -> fp16 (layout preserved)
__global__ void conv_whh_h_kernel(const float* __restrict__ src, __half* __restrict__ dst) {
    int idx = blockIdx.x * 256 + threadIdx.x;
    if (idx < Gg * Hh) dst[idx] = __float2half(src[idx]);
}

__global__ void init_kernel(__half* ha, __half* hb) {
    int i = blockIdx.x * 256 + threadIdx.x;
    if (i == 0) g_bar = 0u;
    if (i < Bsz * Hh) {
        ha[i] = __float2half(0.f);
        hb[i] = __float2half(0.f);
    }
}

// ---------------- xg GEMM (HMMA bf16x3, unchanged) --------------------------
__global__ void __launch_bounds__(256) xg_gemm_kernel(
    const __nv_bfloat16* __restrict__ Ahi, const __nv_bfloat16* __restrict__ Alo,
    const __nv_bfloat16* __restrict__ Bhi, const __nv_bfloat16* __restrict__ Blo,
    const float* __restrict__ bih, const float* __restrict__ bhh,
    float* __restrict__ C)
{
    __shared__ __align__(16) __nv_bfloat16 sA[2][128][40];
    __shared__ __align__(16) __nv_bfloat16 sB[2][32][136];
    const int tid = threadIdx.x;
    const int l = tid & 31, w = tid >> 5;
    const int wm = w >> 1, wn = w & 1;
    const int n0 = blockIdx.x * 128;
    const int m0 = blockIdx.y * 128;

    float acc[2][8][4];
#pragma unroll
    for (int mi = 0; mi < 2; mi++)
#pragma unroll
        for (int nt = 0; nt < 8; nt++)
#pragma unroll
            for (int q = 0; q < 4; q++) acc[mi][nt][q] = 0.f;

    for (int k0 = 0; k0 < Ii; k0 += 32) {
        for (int s = tid; s < 512; s += 256) {
            int row = s >> 2, ch = (s & 3) * 8;
            *(uint4*)&sA[0][row][ch] = *(const uint4*)(Ahi + (size_t)(m0 + row) * Ii + k0 + ch);
            *(uint4*)&sA[1][row][ch] = *(const uint4*)(Alo + (size_t)(m0 + row) * Ii + k0 + ch);
        }
        for (int s = tid; s < 512; s += 256) {
            int kr = s >> 4, ch = (s & 15) * 8;
            *(uint4*)&sB[0][kr][ch] = *(const uint4*)(Bhi + (size_t)(k0 + kr) * Gg + n0 + ch);
            *(uint4*)&sB[1][kr][ch] = *(const uint4*)(Blo + (size_t)(k0 + kr) * Gg + n0 + ch);
        }
        __syncthreads();
#pragma unroll
        for (int kk = 0; kk < 32; kk += 16) {
            uint32_t af[2][2][4];
#pragma unroll
            for (int p = 0; p < 2; p++)
#pragma unroll
                for (int mi = 0; mi < 2; mi++) {
                    uint32_t addr = smem_u32(
                        &sA[p][wm * 32 + mi * 16 + (l & 15)][kk + (l >> 4) * 8]);
                    ldsm4(af[p][mi], addr);
                }
            uint32_t bfr[2][8][2];
            const int krow = (l & 15);
            const int csel = (l >> 4) * 8;
#pragma unroll
            for (int p = 0; p < 2; p++)
#pragma unroll
                for (int jp = 0; jp < 4; jp++) {
                    uint32_t addr = smem_u32(&sB[p][kk + krow][wn * 64 + jp * 16 + csel]);
                    uint32_t r0, r1, r2, r3;
                    ldsm4t(r0, r1, r2, r3, addr);
                    bfr[p][jp * 2][0] = r0; bfr[p][jp * 2][1] = r1;
                    bfr[p][jp * 2 + 1][0] = r2; bfr[p][jp * 2 + 1][1] = r3;
                }
#pragma unroll
            for (int mi = 0; mi < 2; mi++)
#pragma unroll
                for (int nt = 0; nt < 8; nt++) {
                    mma_bf16(acc[mi][nt], af[0][mi], bfr[0][nt]);
                    mma_bf16(acc[mi][nt], af[0][mi], bfr[1][nt]);
                    mma_bf16(acc[mi][nt], af[1][mi], bfr[0][nt]);
                }
        }
        __syncthreads();
    }

    const int r = l >> 2, cq = (l & 3) * 2;
#pragma unroll
    for (int mi = 0; mi < 2; mi++)
#pragma unroll
        for (int nt = 0; nt < 8; nt++) {
            const int col = n0 + wn * 64 + nt * 8 + cq;
            float bs0 = bih[col] + bhh[col];
            float bs1 = bih[col + 1] + bhh[col + 1];
#pragma unroll
            for (int rr = 0; rr < 2; rr++) {
                int m = m0 + wm * 32 + mi * 16 + r + rr * 8;
                float2 v = make_float2(acc[mi][nt][rr * 2 + 0] + bs0,
                                       acc[mi][nt][rr * 2 + 1] + bs1);
                *(float2*)(C + (size_t)m * Gg + col) = v;
            }
        }
}

// ---------------- persistent FP16 scan (single precision pass) --------------
// 128 CTAs = 4 batch tiles (128) x 32 ncol tiles (64 = 4 gates x 16 hcols).
// Whh fp16 RESIDENT in smem; h fp16 staged via 3-stage cp.async; c in registers.
// Warps: 8 x m16, each warp covers all 64 ncols.
// smem: sB [512 k][72 n] fp16 (73728 B) ; sA [stage3][128 m][40] fp16 (3*10240 B)
#define SCAN_SB_OFF   0
#define SCAN_SA_OFF   73728
#define SCAN_SA_SLOT  10240
#define SCAN_SMEM     104448

__global__ void __launch_bounds__(256, 1) scan_f16_kernel(
    const __half* __restrict__ whh,
    __half* __restrict__ hA, __half* __restrict__ hB,
    const float* __restrict__ xg, float* __restrict__ hs)
{
    extern __shared__ __align__(128) char sm[];
    const uint32_t smb = smem_u32(sm);
    const int tid = threadIdx.x, l = tid & 31, w = tid >> 5;
    const int bt = blockIdx.x >> 5;       // batch tile 0..3
    const int ctile = blockIdx.x & 31;    // ncol tile 0..31
    const int mb = bt * 128;
    const int hc0 = ctile * 16;

    // ---- fill resident B: sB[k][n_local], n_local = gate*16 + hcol ----
    {
        __half* dstb = (__half*)(sm + SCAN_SB_OFF);
        for (int s = tid; s < 4096; s += 256) {
            int n = s >> 6;               // 0..63
            int kg = (s & 63) * 8;        // 0..504
            int gate = n >> 4, hc = n & 15;
            const __half* sp = whh + (size_t)(gate * Hh + hc0 + hc) * Hh + kg;
            __half v[8];
            *(uint4*)v = *(const uint4*)sp;
#pragma unroll
            for (int e = 0; e < 8; e++) dstb[(kg + e) * 72 + n] = v[e];
        }
    }
    __syncthreads();

    // per-thread ldsm bases
    const uint32_t aoff = (uint32_t)(((w * 16 + (l & 15)) * 40 + (l >> 4) * 8) * 2);
    const uint32_t boff = (uint32_t)(((l & 15) * 72 + (l >> 4) * 8) * 2);

    float c_reg[8];
#pragma unroll
    for (int q = 0; q < 8; q++) c_reg[q] = 0.f;

    const int a_ep = (l & 3) * 2;           // hcol base for epilogue
    const int r0_ep = mb + w * 16 + (l >> 2);

    for (int t = 0; t < Tt; t++) {
        const __half* rh = (t & 1) ? hB : hA;
        __half* wh = (t & 1) ? hA : hB;

        float acc[8][4];
#pragma unroll
        for (int nf = 0; nf < 8; nf++)
#pragma unroll
            for (int q = 0; q < 4; q++) acc[nf][q] = 0.f;

        // issue chunks 0 and 1 (each chunk: 128 rows x 32 halfs = 512 x 16B)
#pragma unroll
        for (int pc = 0; pc < 2; pc++) {
#pragma unroll
            for (int i = 0; i < 2; i++) {
                int s = tid + i * 256;            // 0..511
                int row = s >> 2, kg = (s & 3) * 8;
                const __half* src = rh + (size_t)(mb + row) * Hh + pc * 32 + kg;
                uint32_t dst = smb + SCAN_SA_OFF + (uint32_t)((pc % 3) * SCAN_SA_SLOT)
                             + (uint32_t)((row * 40 + kg) * 2);
                cpasync16(dst, src);
            }
            CP_COMMIT();
        }

        for (int c = 0; c < 16; c++) {
            if (c + 2 < 16) {
                const int pc = c + 2;
#pragma unroll
                for (int i = 0; i < 2; i++) {
                    int s = tid + i * 256;
                    int row = s >> 2, kg = (s & 3) * 8;
                    const __half* src = rh + (size_t)(mb + row) * Hh + pc * 32 + kg;
                    uint32_t dst = smb + SCAN_SA_OFF + (uint32_t)((pc % 3) * SCAN_SA_SLOT)
                                 + (uint32_t)((row * 40 + kg) * 2);
                    cpasync16(dst, src);
                }
                CP_COMMIT();
                CP_WAIT(2);
            } else if (c == 14) {
                CP_WAIT(1);
            } else {
                CP_WAIT(0);
            }
            __syncthreads();

            const uint32_t aAddr = smb + SCAN_SA_OFF + (uint32_t)((c % 3) * SCAN_SA_SLOT) + aoff;
#pragma unroll
            for (int kk = 0; kk < 32; kk += 16) {
                uint32_t af[4];
                ldsm4(af, aAddr + kk * 2);
                uint32_t bfr[8][2];
                const uint32_t bRow = (uint32_t)((c * 32 + kk) * 144);
#pragma unroll
                for (int jp = 0; jp < 4; jp++) {
                    uint32_t r0, r1, r2, r3;
                    ldsm4t(r0, r1, r2, r3, smb + SCAN_SB_OFF + boff + bRow + jp * 32);
                    bfr[jp * 2][0] = r0; bfr[jp * 2][1] = r1;
                    bfr[jp * 2 + 1][0] = r2; bfr[jp * 2 + 1][1] = r3;
                }
#pragma unroll
                for (int nf = 0; nf < 8; nf++)
                    mma_f16(acc[nf], af, bfr[nf]);
            }
        }

        // ---- gate epilogue: c in regs, all 8 warps ----
#pragma unroll
        for (int rr = 0; rr < 2; rr++) {
            const int b = r0_ep + rr * 8;
            const float* xb = xg + ((size_t)b * Tt + t) * Gg + hc0;
            float pre[4][4];
#pragma unroll
            for (int g = 0; g < 4; g++) {
                float2 f2a = *(const float2*)(xb + g * Hh + a_ep);
                float2 f2b = *(const float2*)(xb + g * Hh + a_ep + 8);
                pre[g][0] = acc[g * 2][rr * 2]         + f2a.x;
                pre[g][1] = acc[g * 2][rr * 2 + 1]     + f2a.y;
                pre[g][2] = acc[g * 2 + 1][rr * 2]     + f2b.x;
                pre[g][3] = acc[g * 2 + 1][rr * 2 + 1] + f2b.y;
            }
            float hn[4];
#pragma unroll
            for (int s = 0; s < 4; s++) {
                float ig = fast_sigmoid(pre[0][s]);
                float fg = fast_sigmoid(pre[1][s]);
                float gg = fast_tanh(pre[2][s]);
                float og = fast_sigmoid(pre[3][s]);
                float cv = fg * c_reg[rr * 4 + s] + ig * gg;
                c_reg[rr * 4 + s] = cv;
                hn[s] = og * fast_tanh(cv);
            }
            float* hrow = hs + ((size_t)b * Tt + t) * Hh + hc0;
            *(float2*)(hrow + a_ep)     = make_float2(hn[0], hn[1]);
            *(float2*)(hrow + a_ep + 8) = make_float2(hn[2], hn[3]);
            __half2 p01, p23;
            p01.x = __float2half(hn[0]); p01.y = __float2half(hn[1]);
            p23.x = __float2half(hn[2]); p23.y = __float2half(hn[3]);
            *(__half2*)(wh + (size_t)b * Hh + hc0 + a_ep)     = p01;
            *(__half2*)(wh + (size_t)b * Hh + hc0 + a_ep + 8) = p23;
        }

        // ---- grid barrier ----
        if (t < Tt - 1) {
            __syncthreads();
            if (tid == 0) {
                __threadfence();
                atomicAdd(&g_bar, 1u);
                const unsigned target = (unsigned)NCTA * (unsigned)(t + 1);
                unsigned v;
                do {
                    asm volatile("ld.acquire.gpu.u32 %0,[%1];" : "=r"(v) : "l"(&g_bar));
                    if (v < target) __nanosleep(32);
                } while (v < target);
            }
            __syncthreads();
        }
    }
}

// ---------------- fused head: fc1 + BN1 + leaky + fc2 + BN2 + relu ---------
#define HEAD_DYN_SMEM ((512 * 32 + 512 * 33) * sizeof(float))

__global__ void __launch_bounds__(256) head_kernel(
    const float* __restrict__ fc1_w, const float* __restrict__ fc1_b,
    const float* __restrict__ fc2_w, const float* __restrict__ fc2_b,
    const float* __restrict__ bn1_g, const float* __restrict__ bn1_b,
    const float* __restrict__ bn2_g, const float* __restrict__ bn2_b,
    float* __restrict__ out)
{
    extern __shared__ float smf[];
    float* fc1t = smf;             // [512][32]
    float* sa   = smf + 512 * 32;  // [512][33]

    __shared__ float red1[8], red2[8];
    __shared__ float zbuf[Bsz];
    __shared__ float fc2s[32];
    __shared__ float stats[4];

    const int t = blockIdx.x;
    const int tid = threadIdx.x;
    const int warp = tid >> 5, lane = tid & 31;

    if (tid < 32) fc2s[tid] = fc2_w[tid];
    for (int idx = tid; idx < 32 * 512; idx += 256) {
        int o = idx >> 9, k = idx & 511;
        fc1t[k * 32 + o] = fc1_w[idx];
    }
    __syncthreads();

    const float bias_o = fc1_b[lane];
    for (int pr = 0; pr < 32; pr++) {
        const int b0 = warp * 64 + pr * 2;
        const int b1 = b0 + 1;
        const float4* r0 = (const float4*)(g_hs + ((size_t)b0 * Tt + t) * Hh);
        const float4* r1 = (const float4*)(g_hs + ((size_t)b1 * Tt + t) * Hh);
        float a0 = bias_o, a1 = bias_o;
#pragma unroll 4
        for (int k4 = 0; k4 < Hh / 4; k4++) {
            float4 v0 = r0[k4], v1 = r1[k4];
            const float* fp = fc1t + (k4 * 4) * 32 + lane;
            float wv;
            wv = fp[0];  a0 += v0.x * wv; a1 += v1.x * wv;
            wv = fp[32]; a0 += v0.y * wv; a1 += v1.y * wv;
            wv = fp[64]; a0 += v0.z * wv; a1 += v1.z * wv;
            wv = fp[96]; a0 += v0.w * wv; a1 += v1.w * wv;
        }
        sa[b0 * 33 + lane] = a0;
        sa[b1 * 33 + lane] = a1;
    }
    __syncthreads();

    float s = 0.f, ss = 0.f;
    for (int idx = tid; idx < Bsz * 32; idx += 256) {
        float v = sa[(idx >> 5) * 33 + (idx & 31)];
        s += v; ss += v * v;
    }
#pragma unroll
    for (int off = 16; off; off >>= 1) {
        s  += __shfl_down_sync(0xffffffffu, s,  off);
        ss += __shfl_down_sync(0xffffffffu, ss, off);
    }
    if (lane == 0) { red1[warp] = s; red2[warp] = ss; }
    __syncthreads();
    if (tid == 0) {
        float S = 0.f, SS = 0.f;
        for (int wv = 0; wv < 8; wv++) { S += red1[wv]; SS += red2[wv]; }
        float m = S / 16384.f;
        float v = SS / 16384.f - m * m;
        stats[0] = m;
        stats[1] = rsqrtf(v + 1e-5f);
    }
    __syncthreads();

    const float m1 = stats[0], inv1 = stats[1];
    const float g1 = bn1_g[t], be1 = bn1_b[t];
    const float f2b = fc2_b[0];

    for (int b = tid; b < Bsz; b += 256) {
        float acc = f2b;
#pragma unroll
        for (int o = 0; o < 32; o++) {
            float a = (sa[b * 33 + o] - m1) * inv1 * g1 + be1;
            a = a > 0.f ? a : 0.1f * a;
            acc += a * fc2s[o];
        }
        zbuf[b] = acc;
    }
    __syncthreads();

    float s2 = 0.f, ss2 = 0.f;
    for (int b = tid; b < Bsz; b += 256) { float v = zbuf[b]; s2 += v; ss2 += v * v; }
#pragma unroll
    for (int off = 16; off; off >>= 1) {
        s2  += __shfl_down_sync(0xffffffffu, s2,  off);
        ss2 += __shfl_down_sync(0xffffffffu, ss2, off);
    }
    if (lane == 0) { red1[warp] = s2; red2[warp] = ss2; }
    __syncthreads();
    if (tid == 0) {
        float S = 0.f, SS = 0.f;
        for (int wv = 0; wv < 8; wv++) { S += red1[wv]; SS += red2[wv]; }
        float m = S / (float)Bsz;
        float v = SS / (float)Bsz - m * m;
        stats[2] = m;
        stats[3] = rsqrtf(v + 1e-5f);
    }
    __syncthreads();

    const float m2 = stats[2], inv2 = stats[3];
    const float g2 = bn2_g[t], be2 = bn2_b[t];
    for (int b = tid; b < Bsz; b += 256) {
        float v = (zbuf[b] - m2) * inv2 * g2 + be2;
        out[(size_t)b * Tt + t] = v > 0.f ? v : 0.f;
    }
}

// ---------------- launch ----------------------------------------------------
extern "C" void kernel_launch(void* const* d_in, const int* in_sizes, int n_in,
                              void* d_out, int out_size)
{
    const float* x     = (const float*)d_in[0];
    const float* Wih   = (const float*)d_in[1];
    const float* Whh   = (const float*)d_in[2];
    const float* bih   = (const float*)d_in[3];
    const float* bhh   = (const float*)d_in[4];
    const float* fc1_w = (const float*)d_in[5];
    const float* fc1_b = (const float*)d_in[6];
    const float* fc2_w = (const float*)d_in[7];
    const float* fc2_b = (const float*)d_in[8];
    const float* bn1_g = (const float*)d_in[9];
    const float* bn1_b = (const float*)d_in[10];
    const float* bn2_g = (const float*)d_in[11];
    const float* bn2_b = (const float*)d_in[12];
    float* out = (float*)d_out;

    cudaFuncSetAttribute(head_kernel, cudaFuncAttributeMaxDynamicSharedMemorySize,
                         (int)HEAD_DYN_SMEM);
    cudaFuncSetAttribute(scan_f16_kernel, cudaFuncAttributeMaxDynamicSharedMemorySize,
                         SCAN_SMEM);

    float *d_xg, *d_hs;
    __nv_bfloat16 *d_xhi, *d_xlo, *d_wihhi, *d_wihlo;
    __half *d_whh, *d_hA, *d_hB;
    cudaGetSymbolAddress((void**)&d_xg,    g_xg);
    cudaGetSymbolAddress((void**)&d_hs,    g_hs);
    cudaGetSymbolAddress((void**)&d_xhi,   g_x_hi);
    cudaGetSymbolAddress((void**)&d_xlo,   g_x_lo);
    cudaGetSymbolAddress((void**)&d_wihhi, g_wih_hi);
    cudaGetSymbolAddress((void**)&d_wihlo, g_wih_lo);
    cudaGetSymbolAddress((void**)&d_whh,   g_whh_h);
    cudaGetSymbolAddress((void**)&d_hA,    g_hA);
    cudaGetSymbolAddress((void**)&d_hB,    g_hB);

    // prep
    conv_w_kernel<<<(Gg * Ii + 255) / 256, 256>>>(Wih, d_wihhi, d_wihlo, Gg, Ii);
    conv_whh_h_kernel<<<(Gg * Hh + 255) / 256, 256>>>(Whh, d_whh);
    conv_x_kernel<<<((int)((size_t)Bsz * Tt * Ii) + 255) / 256, 256>>>(
        x, d_xhi, d_xlo, Bsz * Tt * Ii);
    init_kernel<<<(Bsz * Hh + 255) / 256, 256>>>(d_hA, d_hB);

    // xg = x @ Wih^T + bih + bhh
    xg_gemm_kernel<<<dim3(Gg / 128, (Bsz * Tt) / 128), 256>>>(
        d_xhi, d_xlo, d_wihhi, d_wihlo, bih, bhh, d_xg);

    // persistent FP16 scan (single pass)
    scan_f16_kernel<<<NCTA, 256, SCAN_SMEM>>>(d_whh, d_hA, d_hB, d_xg, d_hs);

    // fused head
    head_kernel<<<Tt, 256, HEAD_DYN_SMEM>>>(fc1_w, fc1_b, fc2_w, fc2_b,
                                            bn1_g, bn1_b, bn2_g, bn2_b, out);
}

// round 11
// speedup vs baseline: 2.0930x; 1.4445x over previous
#include <cuda_runtime.h>
#include <cuda_bf16.h>
#include <cuda_fp16.h>
#include <math.h>
#include <stdint.h>

#define Bsz 512
#define Tt  256
#define Ii  256
#define Hh  512
#define Gg  2048   // 4H
#define NCTA 128   // persistent scan grid

// ---------------- scratch (device globals; no allocation allowed) ----------
__device__ __align__(256) float g_xg[(size_t)Bsz * Tt * Gg];   // 1.07 GB
__device__ __align__(256) float g_hs[(size_t)Bsz * Tt * Hh];   // 256 MB
__device__ __align__(256) __nv_bfloat16 g_x_hi[(size_t)Bsz * Tt * Ii];
__device__ __align__(256) __nv_bfloat16 g_x_lo[(size_t)Bsz * Tt * Ii];
__device__ __align__(256) __nv_bfloat16 g_wih_hi[Ii * Gg];   // transposed [256][2048]
__device__ __align__(256) __nv_bfloat16 g_wih_lo[Ii * Gg];
__device__ __align__(256) __half g_whh_h[Gg * Hh];           // fp16 Whh, plain [2048][512]
__device__ __align__(256) __half g_hA[Bsz * Hh];             // fp16 h, double-buffered
__device__ __align__(256) __half g_hB[Bsz * Hh];
__device__ unsigned g_bar;

// ---------------- PTX helpers ----------------------------------------------
__device__ __forceinline__ uint32_t smem_u32(const void* p) {
    return (uint32_t)__cvta_generic_to_shared(p);
}
__device__ __forceinline__ void ldsm4(uint32_t* r, uint32_t addr) {
    asm volatile("ldmatrix.sync.aligned.m8n8.x4.shared.b16 {%0,%1,%2,%3},[%4];\n"
                 : "=r"(r[0]), "=r"(r[1]), "=r"(r[2]), "=r"(r[3]) : "r"(addr));
}
__device__ __forceinline__ void ldsm4t(uint32_t& r0, uint32_t& r1, uint32_t& r2, uint32_t& r3,
                                       uint32_t addr) {
    asm volatile("ldmatrix.sync.aligned.m8n8.x4.trans.shared.b16 {%0,%1,%2,%3},[%4];\n"
                 : "=r"(r0), "=r"(r1), "=r"(r2), "=r"(r3) : "r"(addr));
}
__device__ __forceinline__ void mma_bf16(float* c, const uint32_t* a, const uint32_t* b) {
    asm volatile("mma.sync.aligned.m16n8k16.row.col.f32.bf16.bf16.f32 "
                 "{%0,%1,%2,%3},{%4,%5,%6,%7},{%8,%9},{%0,%1,%2,%3};\n"
                 : "+f"(c[0]), "+f"(c[1]), "+f"(c[2]), "+f"(c[3])
                 : "r"(a[0]), "r"(a[1]), "r"(a[2]), "r"(a[3]), "r"(b[0]), "r"(b[1]));
}
__device__ __forceinline__ void mma_f16(float* c, const uint32_t* a, const uint32_t* b) {
    asm volatile("mma.sync.aligned.m16n8k16.row.col.f32.f16.f16.f32 "
                 "{%0,%1,%2,%3},{%4,%5,%6,%7},{%8,%9},{%0,%1,%2,%3};\n"
                 : "+f"(c[0]), "+f"(c[1]), "+f"(c[2]), "+f"(c[3])
                 : "r"(a[0]), "r"(a[1]), "r"(a[2]), "r"(a[3]), "r"(b[0]), "r"(b[1]));
}
// 8-byte L2-only load (h crosses the grid barrier between SMs -> bypass L1)
__device__ __forceinline__ uint2 ldcg2(const void* p) {
    uint2 v;
    asm volatile("ld.global.cg.v2.u32 {%0,%1},[%2];\n" : "=r"(v.x), "=r"(v.y) : "l"(p));
    return v;
}

__device__ __forceinline__ float fast_sigmoid(float x) {
    return __fdividef(1.f, 1.f + __expf(-x));
}
__device__ __forceinline__ float fast_tanh(float x) {
    return 1.f - __fdividef(2.f, __expf(2.f * x) + 1.f);
}

// ---------------- prep kernels ---------------------------------------------
// [N][K] fp32 -> transposed [K][N=2048] bf16 hi/lo (for xg GEMM's Wih)
__global__ void conv_w_kernel(const float* __restrict__ src,
                              __nv_bfloat16* __restrict__ dhi,
                              __nv_bfloat16* __restrict__ dlo, int N, int K) {
    int idx = blockIdx.x * 256 + threadIdx.x;
    if (idx >= N * K) return;
    int n = idx / K, k = idx - n * K;
    float v = src[idx];
    __nv_bfloat16 h = __float2bfloat16(v);
    dhi[(size_t)k * Gg + n] = h;
    dlo[(size_t)k * Gg + n] = __float2bfloat16(v - __bfloat162float(h));
}

__global__ void conv_x_kernel(const float* __restrict__ src,
                              __nv_bfloat16* __restrict__ dhi,
                              __nv_bfloat16* __restrict__ dlo, int n) {
    int idx = blockIdx.x * 256 + threadIdx.x;
    if (idx >= n) return;
    float v = src[idx];
    __nv_bfloat16 h = __float2bfloat16(v);
    dhi[idx] = h;
    dlo[idx] = __float2bfloat16(v - __bfloat162float(h));
}

// Whh fp32 -> fp16 (layout preserved)
__global__ void conv_whh_h_kernel(const float* __restrict__ src, __half* __restrict__ dst) {
    int idx = blockIdx.x * 256 + threadIdx.x;
    if (idx < Gg * Hh) dst[idx] = __float2half(src[idx]);
}

__global__ void init_kernel(__half* ha, __half* hb) {
    int i = blockIdx.x * 256 + threadIdx.x;
    if (i == 0) g_bar = 0u;
    if (i < Bsz * Hh) {
        ha[i] = __float2half(0.f);
        hb[i] = __float2half(0.f);
    }
}

// ---------------- xg GEMM (HMMA bf16x3, unchanged) --------------------------
__global__ void __launch_bounds__(256) xg_gemm_kernel(
    const __nv_bfloat16* __restrict__ Ahi, const __nv_bfloat16* __restrict__ Alo,
    const __nv_bfloat16* __restrict__ Bhi, const __nv_bfloat16* __restrict__ Blo,
    const float* __restrict__ bih, const float* __restrict__ bhh,
    float* __restrict__ C)
{
    __shared__ __align__(16) __nv_bfloat16 sA[2][128][40];
    __shared__ __align__(16) __nv_bfloat16 sB[2][32][136];
    const int tid = threadIdx.x;
    const int l = tid & 31, w = tid >> 5;
    const int wm = w >> 1, wn = w & 1;
    const int n0 = blockIdx.x * 128;
    const int m0 = blockIdx.y * 128;

    float acc[2][8][4];
#pragma unroll
    for (int mi = 0; mi < 2; mi++)
#pragma unroll
        for (int nt = 0; nt < 8; nt++)
#pragma unroll
            for (int q = 0; q < 4; q++) acc[mi][nt][q] = 0.f;

    for (int k0 = 0; k0 < Ii; k0 += 32) {
        for (int s = tid; s < 512; s += 256) {
            int row = s >> 2, ch = (s & 3) * 8;
            *(uint4*)&sA[0][row][ch] = *(const uint4*)(Ahi + (size_t)(m0 + row) * Ii + k0 + ch);
            *(uint4*)&sA[1][row][ch] = *(const uint4*)(Alo + (size_t)(m0 + row) * Ii + k0 + ch);
        }
        for (int s = tid; s < 512; s += 256) {
            int kr = s >> 4, ch = (s & 15) * 8;
            *(uint4*)&sB[0][kr][ch] = *(const uint4*)(Bhi + (size_t)(k0 + kr) * Gg + n0 + ch);
            *(uint4*)&sB[1][kr][ch] = *(const uint4*)(Blo + (size_t)(k0 + kr) * Gg + n0 + ch);
        }
        __syncthreads();
#pragma unroll
        for (int kk = 0; kk < 32; kk += 16) {
            uint32_t af[2][2][4];
#pragma unroll
            for (int p = 0; p < 2; p++)
#pragma unroll
                for (int mi = 0; mi < 2; mi++) {
                    uint32_t addr = smem_u32(
                        &sA[p][wm * 32 + mi * 16 + (l & 15)][kk + (l >> 4) * 8]);
                    ldsm4(af[p][mi], addr);
                }
            uint32_t bfr[2][8][2];
            const int krow = (l & 15);
            const int csel = (l >> 4) * 8;
#pragma unroll
            for (int p = 0; p < 2; p++)
#pragma unroll
                for (int jp = 0; jp < 4; jp++) {
                    uint32_t addr = smem_u32(&sB[p][kk + krow][wn * 64 + jp * 16 + csel]);
                    uint32_t r0, r1, r2, r3;
                    ldsm4t(r0, r1, r2, r3, addr);
                    bfr[p][jp * 2][0] = r0; bfr[p][jp * 2][1] = r1;
                    bfr[p][jp * 2 + 1][0] = r2; bfr[p][jp * 2 + 1][1] = r3;
                }
#pragma unroll
            for (int mi = 0; mi < 2; mi++)
#pragma unroll
                for (int nt = 0; nt < 8; nt++) {
                    mma_bf16(acc[mi][nt], af[0][mi], bfr[0][nt]);
                    mma_bf16(acc[mi][nt], af[0][mi], bfr[1][nt]);
                    mma_bf16(acc[mi][nt], af[1][mi], bfr[0][nt]);
                }
        }
        __syncthreads();
    }

    const int r = l >> 2, cq = (l & 3) * 2;
#pragma unroll
    for (int mi = 0; mi < 2; mi++)
#pragma unroll
        for (int nt = 0; nt < 8; nt++) {
            const int col = n0 + wn * 64 + nt * 8 + cq;
            float bs0 = bih[col] + bhh[col];
            float bs1 = bih[col + 1] + bhh[col + 1];
#pragma unroll
            for (int rr = 0; rr < 2; rr++) {
                int m = m0 + wm * 32 + mi * 16 + r + rr * 8;
                float2 v = make_float2(acc[mi][nt][rr * 2 + 0] + bs0,
                                       acc[mi][nt][rr * 2 + 1] + bs1);
                *(float2*)(C + (size_t)m * Gg + col) = v;
            }
        }
}

// ---------------- persistent FP16 scan, A direct-to-register ----------------
// 128 CTAs = 4 batch tiles (128) x 32 ncol tiles (64 = 4 gates x 16 hcols).
// B (Whh slice, fp16) resident in SMEM, rows k-PERMUTED so that the matching
// A fragment is exactly two contiguous 8-byte global loads per lane per k16:
//   frag-k {2q,2q+1,2q+8,2q+9} <-> global k {4q,4q+1,4q+2,4q+3}
// => NO cp.async, NO SMEM staging, NO __syncthreads in the K loop.
// Per step: prefetch xg, 4 K-chunks of 128 (A regs double-buffered), epilogue,
// grid barrier. c lives in registers.
#define SCAN_SMEM (512 * 72 * 2)   // 73728 B: resident B only

__global__ void __launch_bounds__(256, 1) scan_f16r_kernel(
    const __half* __restrict__ whh,
    __half* __restrict__ hA, __half* __restrict__ hB,
    const float* __restrict__ xg, float* __restrict__ hs)
{
    extern __shared__ __align__(128) char sm[];
    const uint32_t smb = smem_u32(sm);
    const int tid = threadIdx.x, l = tid & 31, w = tid >> 5;
    const int bt = blockIdx.x >> 5;       // batch tile 0..3
    const int ctile = blockIdx.x & 31;    // ncol tile 0..31
    const int mb = bt * 128;
    const int hc0 = ctile * 16;

    // ---- fill resident B with per-16-block k-row permutation ----
    {
        __half* sB = (__half*)sm;
        for (int s = tid; s < 64 * 512; s += 256) {
            int n = s >> 9;                // 0..63 (gate*16 + hc)
            int g = s & 511;               // global k
            int gate = n >> 4, hc = n & 15;
            int q = (g & 15) >> 2;
            int r2 = g & 3;
            int f = (g & ~15) + 2 * q + (g & 1) + ((r2 >= 2) ? 8 : 0);
            sB[f * 72 + n] = whh[(size_t)(gate * Hh + hc0 + hc) * Hh + g];
        }
    }
    __syncthreads();

    // per-lane constants
    const int rowA = mb + w * 16 + (l >> 2);
    const size_t offA  = (size_t)rowA * Hh + (l & 3) * 4;   // element offset
    const size_t offA8 = offA + (size_t)8 * Hh;
    const uint32_t bcol = (uint32_t)((l >> 4) * 8) * 2;     // byte col offset
    const uint32_t brow_lane = (uint32_t)(l & 15);

    float c_reg[8];
#pragma unroll
    for (int q = 0; q < 8; q++) c_reg[q] = 0.f;

    const int a_ep = (l & 3) * 2;
    const int r0_ep = rowA;

    for (int t = 0; t < Tt; t++) {
        const __half* rh = (t & 1) ? hB : hA;
        __half* wh = (t & 1) ? hA : hB;

        // ---- issue chunk-0 A loads, then xg prefetch (latency hides under K loop)
        uint2 areg[2][16];
#pragma unroll
        for (int j = 0; j < 8; j++) {
            areg[0][j * 2]     = ldcg2(rh + offA  + j * 16);
            areg[0][j * 2 + 1] = ldcg2(rh + offA8 + j * 16);
        }
        float2 xv[16];
        {
            const float* xb  = xg + ((size_t)r0_ep * Tt + t) * Gg + hc0;
            const float* xb8 = xg + ((size_t)(r0_ep + 8) * Tt + t) * Gg + hc0;
#pragma unroll
            for (int g = 0; g < 4; g++) {
                xv[g * 2]         = *(const float2*)(xb  + g * Hh + a_ep);
                xv[g * 2 + 1]     = *(const float2*)(xb  + g * Hh + a_ep + 8);
                xv[8 + g * 2]     = *(const float2*)(xb8 + g * Hh + a_ep);
                xv[8 + g * 2 + 1] = *(const float2*)(xb8 + g * Hh + a_ep + 8);
            }
        }

        float acc[8][4];
#pragma unroll
        for (int nf = 0; nf < 8; nf++)
#pragma unroll
            for (int q = 0; q < 4; q++) acc[nf][q] = 0.f;

        // ---- 4 K-chunks of 128, register double-buffered, NO syncs ----
#pragma unroll
        for (int c = 0; c < 4; c++) {
            const int buf = c & 1;
            if (c < 3) {
                const int nxt = buf ^ 1;
                const size_t ko = (size_t)(c + 1) * 128;
#pragma unroll
                for (int j = 0; j < 8; j++) {
                    areg[nxt][j * 2]     = ldcg2(rh + offA  + ko + j * 16);
                    areg[nxt][j * 2 + 1] = ldcg2(rh + offA8 + ko + j * 16);
                }
            }
#pragma unroll
            for (int j = 0; j < 8; j++) {
                const uint32_t brow = (uint32_t)((c * 128 + j * 16 + brow_lane) * 72) * 2 + bcol;
                uint32_t bfr[8][2];
#pragma unroll
                for (int jp = 0; jp < 4; jp++) {
                    uint32_t r0, r1, r2, r3;
                    ldsm4t(r0, r1, r2, r3, smb + brow + jp * 32);
                    bfr[jp * 2][0] = r0; bfr[jp * 2][1] = r1;
                    bfr[jp * 2 + 1][0] = r2; bfr[jp * 2 + 1][1] = r3;
                }
                uint32_t a[4];
                a[0] = areg[buf][j * 2].x;
                a[1] = areg[buf][j * 2 + 1].x;
                a[2] = areg[buf][j * 2].y;
                a[3] = areg[buf][j * 2 + 1].y;
#pragma unroll
                for (int nf = 0; nf < 8; nf++)
                    mma_f16(acc[nf], a, bfr[nf]);
            }
        }

        // ---- gate epilogue (c in regs) ----
#pragma unroll
        for (int rr = 0; rr < 2; rr++) {
            const int b = r0_ep + rr * 8;
            float pre[4][4];
#pragma unroll
            for (int g = 0; g < 4; g++) {
                pre[g][0] = acc[g * 2][rr * 2]         + xv[rr * 8 + g * 2].x;
                pre[g][1] = acc[g * 2][rr * 2 + 1]     + xv[rr * 8 + g * 2].y;
                pre[g][2] = acc[g * 2 + 1][rr * 2]     + xv[rr * 8 + g * 2 + 1].x;
                pre[g][3] = acc[g * 2 + 1][rr * 2 + 1] + xv[rr * 8 + g * 2 + 1].y;
            }
            float hn[4];
#pragma unroll
            for (int s = 0; s < 4; s++) {
                float ig = fast_sigmoid(pre[0][s]);
                float fg = fast_sigmoid(pre[1][s]);
                float gg = fast_tanh(pre[2][s]);
                float og = fast_sigmoid(pre[3][s]);
                float cv = fg * c_reg[rr * 4 + s] + ig * gg;
                c_reg[rr * 4 + s] = cv;
                hn[s] = og * fast_tanh(cv);
            }
            float* hrow = hs + ((size_t)b * Tt + t) * Hh + hc0;
            *(float2*)(hrow + a_ep)     = make_float2(hn[0], hn[1]);
            *(float2*)(hrow + a_ep + 8) = make_float2(hn[2], hn[3]);
            __half2 p01, p23;
            p01.x = __float2half(hn[0]); p01.y = __float2half(hn[1]);
            p23.x = __float2half(hn[2]); p23.y = __float2half(hn[3]);
            *(__half2*)(wh + (size_t)b * Hh + hc0 + a_ep)     = p01;
            *(__half2*)(wh + (size_t)b * Hh + hc0 + a_ep + 8) = p23;
        }

        // ---- grid barrier ----
        if (t < Tt - 1) {
            __syncthreads();
            if (tid == 0) {
                __threadfence();
                atomicAdd(&g_bar, 1u);
                const unsigned target = (unsigned)NCTA * (unsigned)(t + 1);
                unsigned v;
                do {
                    asm volatile("ld.acquire.gpu.u32 %0,[%1];" : "=r"(v) : "l"(&g_bar));
                    if (v < target) __nanosleep(32);
                } while (v < target);
            }
            __syncthreads();
        }
    }
}

// ---------------- fused head: fc1 + BN1 + leaky + fc2 + BN2 + relu ---------
#define HEAD_DYN_SMEM ((512 * 32 + 512 * 33) * sizeof(float))

__global__ void __launch_bounds__(256) head_kernel(
    const float* __restrict__ fc1_w, const float* __restrict__ fc1_b,
    const float* __restrict__ fc2_w, const float* __restrict__ fc2_b,
    const float* __restrict__ bn1_g, const float* __restrict__ bn1_b,
    const float* __restrict__ bn2_g, const float* __restrict__ bn2_b,
    float* __restrict__ out)
{
    extern __shared__ float smf[];
    float* fc1t = smf;             // [512][32]
    float* sa   = smf + 512 * 32;  // [512][33]

    __shared__ float red1[8], red2[8];
    __shared__ float zbuf[Bsz];
    __shared__ float fc2s[32];
    __shared__ float stats[4];

    const int t = blockIdx.x;
    const int tid = threadIdx.x;
    const int warp = tid >> 5, lane = tid & 31;

    if (tid < 32) fc2s[tid] = fc2_w[tid];
    for (int idx = tid; idx < 32 * 512; idx += 256) {
        int o = idx >> 9, k = idx & 511;
        fc1t[k * 32 + o] = fc1_w[idx];
    }
    __syncthreads();

    const float bias_o = fc1_b[lane];
    for (int pr = 0; pr < 32; pr++) {
        const int b0 = warp * 64 + pr * 2;
        const int b1 = b0 + 1;
        const float4* r0 = (const float4*)(g_hs + ((size_t)b0 * Tt + t) * Hh);
        const float4* r1 = (const float4*)(g_hs + ((size_t)b1 * Tt + t) * Hh);
        float a0 = bias_o, a1 = bias_o;
#pragma unroll 4
        for (int k4 = 0; k4 < Hh / 4; k4++) {
            float4 v0 = r0[k4], v1 = r1[k4];
            const float* fp = fc1t + (k4 * 4) * 32 + lane;
            float wv;
            wv = fp[0];  a0 += v0.x * wv; a1 += v1.x * wv;
            wv = fp[32]; a0 += v0.y * wv; a1 += v1.y * wv;
            wv = fp[64]; a0 += v0.z * wv; a1 += v1.z * wv;
            wv = fp[96]; a0 += v0.w * wv; a1 += v1.w * wv;
        }
        sa[b0 * 33 + lane] = a0;
        sa[b1 * 33 + lane] = a1;
    }
    __syncthreads();

    float s = 0.f, ss = 0.f;
    for (int idx = tid; idx < Bsz * 32; idx += 256) {
        float v = sa[(idx >> 5) * 33 + (idx & 31)];
        s += v; ss += v * v;
    }
#pragma unroll
    for (int off = 16; off; off >>= 1) {
        s  += __shfl_down_sync(0xffffffffu, s,  off);
        ss += __shfl_down_sync(0xffffffffu, ss, off);
    }
    if (lane == 0) { red1[warp] = s; red2[warp] = ss; }
    __syncthreads();
    if (tid == 0) {
        float S = 0.f, SS = 0.f;
        for (int wv = 0; wv < 8; wv++) { S += red1[wv]; SS += red2[wv]; }
        float m = S / 16384.f;
        float v = SS / 16384.f - m * m;
        stats[0] = m;
        stats[1] = rsqrtf(v + 1e-5f);
    }
    __syncthreads();

    const float m1 = stats[0], inv1 = stats[1];
    const float g1 = bn1_g[t], be1 = bn1_b[t];
    const float f2b = fc2_b[0];

    for (int b = tid; b < Bsz; b += 256) {
        float acc = f2b;
#pragma unroll
        for (int o = 0; o < 32; o++) {
            float a = (sa[b * 33 + o] - m1) * inv1 * g1 + be1;
            a = a > 0.f ? a : 0.1f * a;
            acc += a * fc2s[o];
        }
        zbuf[b] = acc;
    }
    __syncthreads();

    float s2 = 0.f, ss2 = 0.f;
    for (int b = tid; b < Bsz; b += 256) { float v = zbuf[b]; s2 += v; ss2 += v * v; }
#pragma unroll
    for (int off = 16; off; off >>= 1) {
        s2  += __shfl_down_sync(0xffffffffu, s2,  off);
        ss2 += __shfl_down_sync(0xffffffffu, ss2, off);
    }
    if (lane == 0) { red1[warp] = s2; red2[warp] = ss2; }
    __syncthreads();
    if (tid == 0) {
        float S = 0.f, SS = 0.f;
        for (int wv = 0; wv < 8; wv++) { S += red1[wv]; SS += red2[wv]; }
        float m = S / (float)Bsz;
        float v = SS / (float)Bsz - m * m;
        stats[2] = m;
        stats[3] = rsqrtf(v + 1e-5f);
    }
    __syncthreads();

    const float m2 = stats[2], inv2 = stats[3];
    const float g2 = bn2_g[t], be2 = bn2_b[t];
    for (int b = tid; b < Bsz; b += 256) {
        float v = (zbuf[b] - m2) * inv2 * g2 + be2;
        out[(size_t)b * Tt + t] = v > 0.f ? v : 0.f;
    }
}

// ---------------- launch ----------------------------------------------------
extern "C" void kernel_launch(void* const* d_in, const int* in_sizes, int n_in,
                              void* d_out, int out_size)
{
    const float* x     = (const float*)d_in[0];
    const float* Wih   = (const float*)d_in[1];
    const float* Whh   = (const float*)d_in[2];
    const float* bih   = (const float*)d_in[3];
    const float* bhh   = (const float*)d_in[4];
    const float* fc1_w = (const float*)d_in[5];
    const float* fc1_b = (const float*)d_in[6];
    const float* fc2_w = (const float*)d_in[7];
    const float* fc2_b = (const float*)d_in[8];
    const float* bn1_g = (const float*)d_in[9];
    const float* bn1_b = (const float*)d_in[10];
    const float* bn2_g = (const float*)d_in[11];
    const float* bn2_b = (const float*)d_in[12];
    float* out = (float*)d_out;

    cudaFuncSetAttribute(head_kernel, cudaFuncAttributeMaxDynamicSharedMemorySize,
                         (int)HEAD_DYN_SMEM);
    cudaFuncSetAttribute(scan_f16r_kernel, cudaFuncAttributeMaxDynamicSharedMemorySize,
                         SCAN_SMEM);

    float *d_xg, *d_hs;
    __nv_bfloat16 *d_xhi, *d_xlo, *d_wihhi, *d_wihlo;
    __half *d_whh, *d_hA, *d_hB;
    cudaGetSymbolAddress((void**)&d_xg,    g_xg);
    cudaGetSymbolAddress((void**)&d_hs,    g_hs);
    cudaGetSymbolAddress((void**)&d_xhi,   g_x_hi);
    cudaGetSymbolAddress((void**)&d_xlo,   g_x_lo);
    cudaGetSymbolAddress((void**)&d_wihhi, g_wih_hi);
    cudaGetSymbolAddress((void**)&d_wihlo, g_wih_lo);
    cudaGetSymbolAddress((void**)&d_whh,   g_whh_h);
    cudaGetSymbolAddress((void**)&d_hA,    g_hA);
    cudaGetSymbolAddress((void**)&d_hB,    g_hB);

    // prep
    conv_w_kernel<<<(Gg * Ii + 255) / 256, 256>>>(Wih, d_wihhi, d_wihlo, Gg, Ii);
    conv_whh_h_kernel<<<(Gg * Hh + 255) / 256, 256>>>(Whh, d_whh);
    conv_x_kernel<<<((int)((size_t)Bsz * Tt * Ii) + 255) / 256, 256>>>(
        x, d_xhi, d_xlo, Bsz * Tt * Ii);
    init_kernel<<<(Bsz * Hh + 255) / 256, 256>>>(d_hA, d_hB);

    // xg = x @ Wih^T + bih + bhh
    xg_gemm_kernel<<<dim3(Gg / 128, (Bsz * Tt) / 128), 256>>>(
        d_xhi, d_xlo, d_wihhi, d_wihlo, bih, bhh, d_xg);

    // persistent FP16 scan, A direct-to-register
    scan_f16r_kernel<<<NCTA, 256, SCAN_SMEM>>>(d_whh, d_hA, d_hB, d_xg, d_hs);

    // fused head
    head_kernel<<<Tt, 256, HEAD_DYN_SMEM>>>(fc1_w, fc1_b, fc2_w, fc2_b,
                                            bn1_g, bn1_b, bn2_g, bn2_b, out);
}

// round 12
// speedup vs baseline: 2.6913x; 1.2858x over previous
#include <cuda_runtime.h>
#include <cuda_bf16.h>
#include <cuda_fp16.h>
#include <math.h>
#include <stdint.h>

#define Bsz 512
#define Tt  256
#define Ii  256
#define Hh  512
#define Gg  2048   // 4H
#define NCTA 128   // persistent scan grid

// ---------------- scratch (device globals; no allocation allowed) ----------
__device__ __align__(256) float g_xg[(size_t)Bsz * Tt * Gg];   // 1.07 GB
__device__ __align__(256) float g_hs[(size_t)Bsz * Tt * Hh];   // 256 MB
__device__ __align__(256) __half g_x_h[(size_t)Bsz * Tt * Ii];  // fp16 x
__device__ __align__(256) __half g_wih_h[Ii * Gg];              // fp16 Wih transposed [256][2048]
__device__ __align__(256) __half g_whh_h[Gg * Hh];              // fp16 Whh, plain [2048][512]
__device__ __align__(256) __half g_hA[Bsz * Hh];                // fp16 h, double-buffered
__device__ __align__(256) __half g_hB[Bsz * Hh];
__device__ unsigned g_bar;

// ---------------- PTX helpers ----------------------------------------------
__device__ __forceinline__ uint32_t smem_u32(const void* p) {
    return (uint32_t)__cvta_generic_to_shared(p);
}
__device__ __forceinline__ void ldsm4(uint32_t* r, uint32_t addr) {
    asm volatile("ldmatrix.sync.aligned.m8n8.x4.shared.b16 {%0,%1,%2,%3},[%4];\n"
                 : "=r"(r[0]), "=r"(r[1]), "=r"(r[2]), "=r"(r[3]) : "r"(addr));
}
__device__ __forceinline__ void ldsm4t(uint32_t& r0, uint32_t& r1, uint32_t& r2, uint32_t& r3,
                                       uint32_t addr) {
    asm volatile("ldmatrix.sync.aligned.m8n8.x4.trans.shared.b16 {%0,%1,%2,%3},[%4];\n"
                 : "=r"(r0), "=r"(r1), "=r"(r2), "=r"(r3) : "r"(addr));
}
__device__ __forceinline__ void mma_f16(float* c, const uint32_t* a, const uint32_t* b) {
    asm volatile("mma.sync.aligned.m16n8k16.row.col.f32.f16.f16.f32 "
                 "{%0,%1,%2,%3},{%4,%5,%6,%7},{%8,%9},{%0,%1,%2,%3};\n"
                 : "+f"(c[0]), "+f"(c[1]), "+f"(c[2]), "+f"(c[3])
                 : "r"(a[0]), "r"(a[1]), "r"(a[2]), "r"(a[3]), "r"(b[0]), "r"(b[1]));
}
// 8-byte L2-only load (h crosses the grid barrier between SMs -> bypass L1)
__device__ __forceinline__ uint2 ldcg2(const void* p) {
    uint2 v;
    asm volatile("ld.global.cg.v2.u32 {%0,%1},[%2];\n" : "=r"(v.x), "=r"(v.y) : "l"(p));
    return v;
}

__device__ __forceinline__ float fast_sigmoid(float x) {
    return __fdividef(1.f, 1.f + __expf(-x));
}
__device__ __forceinline__ float fast_tanh(float x) {
    return 1.f - __fdividef(2.f, __expf(2.f * x) + 1.f);
}

// ---------------- prep kernels ---------------------------------------------
// [N][K] fp32 -> transposed [K][N=2048] fp16 (for xg GEMM's Wih)
__global__ void conv_wih_h_kernel(const float* __restrict__ src,
                                  __half* __restrict__ dst) {
    int idx = blockIdx.x * 256 + threadIdx.x;
    if (idx >= Gg * Ii) return;
    int n = idx / Ii, k = idx - n * Ii;
    dst[(size_t)k * Gg + n] = __float2half(src[idx]);
}

// elementwise fp32 -> fp16
__global__ void conv_h_kernel(const float* __restrict__ src, __half* __restrict__ dst, int n) {
    int idx = blockIdx.x * 256 + threadIdx.x;
    if (idx < n) dst[idx] = __float2half(src[idx]);
}

__global__ void init_kernel(__half* ha, __half* hb) {
    int i = blockIdx.x * 256 + threadIdx.x;
    if (i == 0) g_bar = 0u;
    if (i < Bsz * Hh) {
        ha[i] = __float2half(0.f);
        hb[i] = __float2half(0.f);
    }
}

// ---------------- xg GEMM: C = x @ Wih^T + bih + bhh (fp16 single-pass) -----
__global__ void __launch_bounds__(256) xg_gemm_kernel(
    const __half* __restrict__ A,       // [B*T][256] fp16
    const __half* __restrict__ Bw,      // [256][2048] fp16 (transposed Wih)
    const float* __restrict__ bih, const float* __restrict__ bhh,
    float* __restrict__ C)
{
    __shared__ __align__(16) __half sA[128][40];
    __shared__ __align__(16) __half sB[32][136];
    const int tid = threadIdx.x;
    const int l = tid & 31, w = tid >> 5;
    const int wm = w >> 1, wn = w & 1;
    const int n0 = blockIdx.x * 128;
    const int m0 = blockIdx.y * 128;

    float acc[2][8][4];
#pragma unroll
    for (int mi = 0; mi < 2; mi++)
#pragma unroll
        for (int nt = 0; nt < 8; nt++)
#pragma unroll
            for (int q = 0; q < 4; q++) acc[mi][nt][q] = 0.f;

    for (int k0 = 0; k0 < Ii; k0 += 32) {
        for (int s = tid; s < 512; s += 256) {
            int row = s >> 2, ch = (s & 3) * 8;
            *(uint4*)&sA[row][ch] = *(const uint4*)(A + (size_t)(m0 + row) * Ii + k0 + ch);
        }
        for (int s = tid; s < 512; s += 256) {
            int kr = s >> 4, ch = (s & 15) * 8;
            *(uint4*)&sB[kr][ch] = *(const uint4*)(Bw + (size_t)(k0 + kr) * Gg + n0 + ch);
        }
        __syncthreads();
#pragma unroll
        for (int kk = 0; kk < 32; kk += 16) {
            uint32_t af[2][4];
#pragma unroll
            for (int mi = 0; mi < 2; mi++) {
                uint32_t addr = smem_u32(
                    &sA[wm * 32 + mi * 16 + (l & 15)][kk + (l >> 4) * 8]);
                ldsm4(af[mi], addr);
            }
            uint32_t bfr[8][2];
            const int krow = (l & 15);
            const int csel = (l >> 4) * 8;
#pragma unroll
            for (int jp = 0; jp < 4; jp++) {
                uint32_t addr = smem_u32(&sB[kk + krow][wn * 64 + jp * 16 + csel]);
                uint32_t r0, r1, r2, r3;
                ldsm4t(r0, r1, r2, r3, addr);
                bfr[jp * 2][0] = r0; bfr[jp * 2][1] = r1;
                bfr[jp * 2 + 1][0] = r2; bfr[jp * 2 + 1][1] = r3;
            }
#pragma unroll
            for (int mi = 0; mi < 2; mi++)
#pragma unroll
                for (int nt = 0; nt < 8; nt++)
                    mma_f16(acc[mi][nt], af[mi], bfr[nt]);
        }
        __syncthreads();
    }

    const int r = l >> 2, cq = (l & 3) * 2;
#pragma unroll
    for (int mi = 0; mi < 2; mi++)
#pragma unroll
        for (int nt = 0; nt < 8; nt++) {
            const int col = n0 + wn * 64 + nt * 8 + cq;
            float bs0 = bih[col] + bhh[col];
            float bs1 = bih[col + 1] + bhh[col + 1];
#pragma unroll
            for (int rr = 0; rr < 2; rr++) {
                int m = m0 + wm * 32 + mi * 16 + r + rr * 8;
                float2 v = make_float2(acc[mi][nt][rr * 2 + 0] + bs0,
                                       acc[mi][nt][rr * 2 + 1] + bs1);
                *(float2*)(C + (size_t)m * Gg + col) = v;
            }
        }
}

// ---------------- persistent FP16 scan, A direct-to-register (unchanged) ----
#define SCAN_SMEM (512 * 72 * 2)   // 73728 B: resident B only

__global__ void __launch_bounds__(256, 1) scan_f16r_kernel(
    const __half* __restrict__ whh,
    __half* __restrict__ hA, __half* __restrict__ hB,
    const float* __restrict__ xg, float* __restrict__ hs)
{
    extern __shared__ __align__(128) char sm[];
    const uint32_t smb = smem_u32(sm);
    const int tid = threadIdx.x, l = tid & 31, w = tid >> 5;
    const int bt = blockIdx.x >> 5;       // batch tile 0..3
    const int ctile = blockIdx.x & 31;    // ncol tile 0..31
    const int mb = bt * 128;
    const int hc0 = ctile * 16;

    // ---- fill resident B with per-16-block k-row permutation ----
    {
        __half* sB = (__half*)sm;
        for (int s = tid; s < 64 * 512; s += 256) {
            int n = s >> 9;                // 0..63 (gate*16 + hc)
            int g = s & 511;               // global k
            int gate = n >> 4, hc = n & 15;
            int q = (g & 15) >> 2;
            int r2 = g & 3;
            int f = (g & ~15) + 2 * q + (g & 1) + ((r2 >= 2) ? 8 : 0);
            sB[f * 72 + n] = whh[(size_t)(gate * Hh + hc0 + hc) * Hh + g];
        }
    }
    __syncthreads();

    // per-lane constants
    const int rowA = mb + w * 16 + (l >> 2);
    const size_t offA  = (size_t)rowA * Hh + (l & 3) * 4;   // element offset
    const size_t offA8 = offA + (size_t)8 * Hh;
    const uint32_t bcol = (uint32_t)((l >> 4) * 8) * 2;     // byte col offset
    const uint32_t brow_lane = (uint32_t)(l & 15);

    float c_reg[8];
#pragma unroll
    for (int q = 0; q < 8; q++) c_reg[q] = 0.f;

    const int a_ep = (l & 3) * 2;
    const int r0_ep = rowA;

    for (int t = 0; t < Tt; t++) {
        const __half* rh = (t & 1) ? hB : hA;
        __half* wh = (t & 1) ? hA : hB;

        // ---- issue chunk-0 A loads, then xg prefetch (latency hides under K loop)
        uint2 areg[2][16];
#pragma unroll
        for (int j = 0; j < 8; j++) {
            areg[0][j * 2]     = ldcg2(rh + offA  + j * 16);
            areg[0][j * 2 + 1] = ldcg2(rh + offA8 + j * 16);
        }
        float2 xv[16];
        {
            const float* xb  = xg + ((size_t)r0_ep * Tt + t) * Gg + hc0;
            const float* xb8 = xg + ((size_t)(r0_ep + 8) * Tt + t) * Gg + hc0;
#pragma unroll
            for (int g = 0; g < 4; g++) {
                xv[g * 2]         = *(const float2*)(xb  + g * Hh + a_ep);
                xv[g * 2 + 1]     = *(const float2*)(xb  + g * Hh + a_ep + 8);
                xv[8 + g * 2]     = *(const float2*)(xb8 + g * Hh + a_ep);
                xv[8 + g * 2 + 1] = *(const float2*)(xb8 + g * Hh + a_ep + 8);
            }
        }

        float acc[8][4];
#pragma unroll
        for (int nf = 0; nf < 8; nf++)
#pragma unroll
            for (int q = 0; q < 4; q++) acc[nf][q] = 0.f;

        // ---- 4 K-chunks of 128, register double-buffered, NO syncs ----
#pragma unroll
        for (int c = 0; c < 4; c++) {
            const int buf = c & 1;
            if (c < 3) {
                const int nxt = buf ^ 1;
                const size_t ko = (size_t)(c + 1) * 128;
#pragma unroll
                for (int j = 0; j < 8; j++) {
                    areg[nxt][j * 2]     = ldcg2(rh + offA  + ko + j * 16);
                    areg[nxt][j * 2 + 1] = ldcg2(rh + offA8 + ko + j * 16);
                }
            }
#pragma unroll
            for (int j = 0; j < 8; j++) {
                const uint32_t brow = (uint32_t)((c * 128 + j * 16 + brow_lane) * 72) * 2 + bcol;
                uint32_t bfr[8][2];
#pragma unroll
                for (int jp = 0; jp < 4; jp++) {
                    uint32_t r0, r1, r2, r3;
                    ldsm4t(r0, r1, r2, r3, smb + brow + jp * 32);
                    bfr[jp * 2][0] = r0; bfr[jp * 2][1] = r1;
                    bfr[jp * 2 + 1][0] = r2; bfr[jp * 2 + 1][1] = r3;
                }
                uint32_t a[4];
                a[0] = areg[buf][j * 2].x;
                a[1] = areg[buf][j * 2 + 1].x;
                a[2] = areg[buf][j * 2].y;
                a[3] = areg[buf][j * 2 + 1].y;
#pragma unroll
                for (int nf = 0; nf < 8; nf++)
                    mma_f16(acc[nf], a, bfr[nf]);
            }
        }

        // ---- gate epilogue (c in regs) ----
#pragma unroll
        for (int rr = 0; rr < 2; rr++) {
            const int b = r0_ep + rr * 8;
            float pre[4][4];
#pragma unroll
            for (int g = 0; g < 4; g++) {
                pre[g][0] = acc[g * 2][rr * 2]         + xv[rr * 8 + g * 2].x;
                pre[g][1] = acc[g * 2][rr * 2 + 1]     + xv[rr * 8 + g * 2].y;
                pre[g][2] = acc[g * 2 + 1][rr * 2]     + xv[rr * 8 + g * 2 + 1].x;
                pre[g][3] = acc[g * 2 + 1][rr * 2 + 1] + xv[rr * 8 + g * 2 + 1].y;
            }
            float hn[4];
#pragma unroll
            for (int s = 0; s < 4; s++) {
                float ig = fast_sigmoid(pre[0][s]);
                float fg = fast_sigmoid(pre[1][s]);
                float gg = fast_tanh(pre[2][s]);
                float og = fast_sigmoid(pre[3][s]);
                float cv = fg * c_reg[rr * 4 + s] + ig * gg;
                c_reg[rr * 4 + s] = cv;
                hn[s] = og * fast_tanh(cv);
            }
            float* hrow = hs + ((size_t)b * Tt + t) * Hh + hc0;
            *(float2*)(hrow + a_ep)     = make_float2(hn[0], hn[1]);
            *(float2*)(hrow + a_ep + 8) = make_float2(hn[2], hn[3]);
            __half2 p01, p23;
            p01.x = __float2half(hn[0]); p01.y = __float2half(hn[1]);
            p23.x = __float2half(hn[2]); p23.y = __float2half(hn[3]);
            *(__half2*)(wh + (size_t)b * Hh + hc0 + a_ep)     = p01;
            *(__half2*)(wh + (size_t)b * Hh + hc0 + a_ep + 8) = p23;
        }

        // ---- grid barrier ----
        if (t < Tt - 1) {
            __syncthreads();
            if (tid == 0) {
                __threadfence();
                atomicAdd(&g_bar, 1u);
                const unsigned target = (unsigned)NCTA * (unsigned)(t + 1);
                unsigned v;
                do {
                    asm volatile("ld.acquire.gpu.u32 %0,[%1];" : "=r"(v) : "l"(&g_bar));
                    if (v < target) __nanosleep(32);
                } while (v < target);
            }
            __syncthreads();
        }
    }
}

// ---------------- fused head: fc1 + BN1 + leaky + fc2 + BN2 + relu ---------
#define HEAD_DYN_SMEM ((512 * 32 + 512 * 33) * sizeof(float))

__global__ void __launch_bounds__(256) head_kernel(
    const float* __restrict__ fc1_w, const float* __restrict__ fc1_b,
    const float* __restrict__ fc2_w, const float* __restrict__ fc2_b,
    const float* __restrict__ bn1_g, const float* __restrict__ bn1_b,
    const float* __restrict__ bn2_g, const float* __restrict__ bn2_b,
    float* __restrict__ out)
{
    extern __shared__ float smf[];
    float* fc1t = smf;             // [512][32]
    float* sa   = smf + 512 * 32;  // [512][33]

    __shared__ float red1[8], red2[8];
    __shared__ float zbuf[Bsz];
    __shared__ float fc2s[32];
    __shared__ float stats[4];

    const int t = blockIdx.x;
    const int tid = threadIdx.x;
    const int warp = tid >> 5, lane = tid & 31;

    if (tid < 32) fc2s[tid] = fc2_w[tid];
    for (int idx = tid; idx < 32 * 512; idx += 256) {
        int o = idx >> 9, k = idx & 511;
        fc1t[k * 32 + o] = fc1_w[idx];
    }
    __syncthreads();

    const float bias_o = fc1_b[lane];
    for (int pr = 0; pr < 32; pr++) {
        const int b0 = warp * 64 + pr * 2;
        const int b1 = b0 + 1;
        const float4* r0 = (const float4*)(g_hs + ((size_t)b0 * Tt + t) * Hh);
        const float4* r1 = (const float4*)(g_hs + ((size_t)b1 * Tt + t) * Hh);
        float a0 = bias_o, a1 = bias_o;
#pragma unroll 4
        for (int k4 = 0; k4 < Hh / 4; k4++) {
            float4 v0 = r0[k4], v1 = r1[k4];
            const float* fp = fc1t + (k4 * 4) * 32 + lane;
            float wv;
            wv = fp[0];  a0 += v0.x * wv; a1 += v1.x * wv;
            wv = fp[32]; a0 += v0.y * wv; a1 += v1.y * wv;
            wv = fp[64]; a0 += v0.z * wv; a1 += v1.z * wv;
            wv = fp[96]; a0 += v0.w * wv; a1 += v1.w * wv;
        }
        sa[b0 * 33 + lane] = a0;
        sa[b1 * 33 + lane] = a1;
    }
    __syncthreads();

    float s = 0.f, ss = 0.f;
    for (int idx = tid; idx < Bsz * 32; idx += 256) {
        float v = sa[(idx >> 5) * 33 + (idx & 31)];
        s += v; ss += v * v;
    }
#pragma unroll
    for (int off = 16; off; off >>= 1) {
        s  += __shfl_down_sync(0xffffffffu, s,  off);
        ss += __shfl_down_sync(0xffffffffu, ss, off);
    }
    if (lane == 0) { red1[warp] = s; red2[warp] = ss; }
    __syncthreads();
    if (tid == 0) {
        float S = 0.f, SS = 0.f;
        for (int wv = 0; wv < 8; wv++) { S += red1[wv]; SS += red2[wv]; }
        float m = S / 16384.f;
        float v = SS / 16384.f - m * m;
        stats[0] = m;
        stats[1] = rsqrtf(v + 1e-5f);
    }
    __syncthreads();

    const float m1 = stats[0], inv1 = stats[1];
    const float g1 = bn1_g[t], be1 = bn1_b[t];
    const float f2b = fc2_b[0];

    for (int b = tid; b < Bsz; b += 256) {
        float acc = f2b;
#pragma unroll
        for (int o = 0; o < 32; o++) {
            float a = (sa[b * 33 + o] - m1) * inv1 * g1 + be1;
            a = a > 0.f ? a : 0.1f * a;
            acc += a * fc2s[o];
        }
        zbuf[b] = acc;
    }
    __syncthreads();

    float s2 = 0.f, ss2 = 0.f;
    for (int b = tid; b < Bsz; b += 256) { float v = zbuf[b]; s2 += v; ss2 += v * v; }
#pragma unroll
    for (int off = 16; off; off >>= 1) {
        s2  += __shfl_down_sync(0xffffffffu, s2,  off);
        ss2 += __shfl_down_sync(0xffffffffu, ss2, off);
    }
    if (lane == 0) { red1[warp] = s2; red2[warp] = ss2; }
    __syncthreads();
    if (tid == 0) {
        float S = 0.f, SS = 0.f;
        for (int wv = 0; wv < 8; wv++) { S += red1[wv]; SS += red2[wv]; }
        float m = S / (float)Bsz;
        float v = SS / (float)Bsz - m * m;
        stats[2] = m;
        stats[3] = rsqrtf(v + 1e-5f);
    }
    __syncthreads();

    const float m2 = stats[2], inv2 = stats[3];
    const float g2 = bn2_g[t], be2 = bn2_b[t];
    for (int b = tid; b < Bsz; b += 256) {
        float v = (zbuf[b] - m2) * inv2 * g2 + be2;
        out[(size_t)b * Tt + t] = v > 0.f ? v : 0.f;
    }
}

// ---------------- launch ----------------------------------------------------
extern "C" void kernel_launch(void* const* d_in, const int* in_sizes, int n_in,
                              void* d_out, int out_size)
{
    const float* x     = (const float*)d_in[0];
    const float* Wih   = (const float*)d_in[1];
    const float* Whh   = (const float*)d_in[2];
    const float* bih   = (const float*)d_in[3];
    const float* bhh   = (const float*)d_in[4];
    const float* fc1_w = (const float*)d_in[5];
    const float* fc1_b = (const float*)d_in[6];
    const float* fc2_w = (const float*)d_in[7];
    const float* fc2_b = (const float*)d_in[8];
    const float* bn1_g = (const float*)d_in[9];
    const float* bn1_b = (const float*)d_in[10];
    const float* bn2_g = (const float*)d_in[11];
    const float* bn2_b = (const float*)d_in[12];
    float* out = (float*)d_out;

    cudaFuncSetAttribute(head_kernel, cudaFuncAttributeMaxDynamicSharedMemorySize,
                         (int)HEAD_DYN_SMEM);
    cudaFuncSetAttribute(scan_f16r_kernel, cudaFuncAttributeMaxDynamicSharedMemorySize,
                         SCAN_SMEM);

    float *d_xg, *d_hs;
    __half *d_xh, *d_wih, *d_whh, *d_hA, *d_hB;
    cudaGetSymbolAddress((void**)&d_xg,  g_xg);
    cudaGetSymbolAddress((void**)&d_hs,  g_hs);
    cudaGetSymbolAddress((void**)&d_xh,  g_x_h);
    cudaGetSymbolAddress((void**)&d_wih, g_wih_h);
    cudaGetSymbolAddress((void**)&d_whh, g_whh_h);
    cudaGetSymbolAddress((void**)&d_hA,  g_hA);
    cudaGetSymbolAddress((void**)&d_hB,  g_hB);

    // prep
    conv_wih_h_kernel<<<(Gg * Ii + 255) / 256, 256>>>(Wih, d_wih);
    conv_h_kernel<<<(Gg * Hh + 255) / 256, 256>>>(Whh, d_whh, Gg * Hh);
    conv_h_kernel<<<((int)((size_t)Bsz * Tt * Ii) + 255) / 256, 256>>>(
        x, d_xh, Bsz * Tt * Ii);
    init_kernel<<<(Bsz * Hh + 255) / 256, 256>>>(d_hA, d_hB);

    // xg = x @ Wih^T + bih + bhh (fp16 single-pass)
    xg_gemm_kernel<<<dim3(Gg / 128, (Bsz * Tt) / 128), 256>>>(
        d_xh, d_wih, bih, bhh, d_xg);

    // persistent FP16 scan, A direct-to-register
    scan_f16r_kernel<<<NCTA, 256, SCAN_SMEM>>>(d_whh, d_hA, d_hB, d_xg, d_hs);

    // fused head
    head_kernel<<<Tt, 256, HEAD_DYN_SMEM>>>(fc1_w, fc1_b, fc2_w, fc2_b,
                                            bn1_g, bn1_b, bn2_g, bn2_b, out);
}

// round 13
// speedup vs baseline: 3.0217x; 1.1228x over previous
#include <cuda_runtime.h>
#include <cuda_fp16.h>
#include <math.h>
#include <stdint.h>

#define Bsz 512
#define Tt  256
#define Ii  256
#define Hh  512
#define Gg  2048   // 4H
#define NCTA 128   // persistent scan grid

// ---------------- scratch (device globals; no allocation allowed) ----------
__device__ __align__(256) float g_xg[(size_t)Bsz * Tt * Gg];   // 1.07 GB
__device__ __align__(256) __half g_hs[(size_t)Bsz * Tt * Hh];  // 128 MB fp16 hidden states
__device__ __align__(256) __half g_wih_h[Ii * Gg];             // fp16 Wih transposed [256][2048]
__device__ __align__(256) __half g_whh_h[Gg * Hh];             // fp16 Whh, plain [2048][512]
__device__ __align__(256) __half g_hA[Bsz * Hh];               // fp16 h, double-buffered
__device__ __align__(256) __half g_hB[Bsz * Hh];
__device__ unsigned g_bar[4];   // per-batch-tile barrier counters

// ---------------- PTX helpers ----------------------------------------------
__device__ __forceinline__ uint32_t smem_u32(const void* p) {
    return (uint32_t)__cvta_generic_to_shared(p);
}
__device__ __forceinline__ void ldsm4(uint32_t* r, uint32_t addr) {
    asm volatile("ldmatrix.sync.aligned.m8n8.x4.shared.b16 {%0,%1,%2,%3},[%4];\n"
                 : "=r"(r[0]), "=r"(r[1]), "=r"(r[2]), "=r"(r[3]) : "r"(addr));
}
__device__ __forceinline__ void ldsm4t(uint32_t& r0, uint32_t& r1, uint32_t& r2, uint32_t& r3,
                                       uint32_t addr) {
    asm volatile("ldmatrix.sync.aligned.m8n8.x4.trans.shared.b16 {%0,%1,%2,%3},[%4];\n"
                 : "=r"(r0), "=r"(r1), "=r"(r2), "=r"(r3) : "r"(addr));
}
__device__ __forceinline__ void mma_f16(float* c, const uint32_t* a, const uint32_t* b) {
    asm volatile("mma.sync.aligned.m16n8k16.row.col.f32.f16.f16.f32 "
                 "{%0,%1,%2,%3},{%4,%5,%6,%7},{%8,%9},{%0,%1,%2,%3};\n"
                 : "+f"(c[0]), "+f"(c[1]), "+f"(c[2]), "+f"(c[3])
                 : "r"(a[0]), "r"(a[1]), "r"(a[2]), "r"(a[3]), "r"(b[0]), "r"(b[1]));
}
// 8-byte L2-only load (h crosses the barrier between SMs -> bypass L1)
__device__ __forceinline__ uint2 ldcg2(const void* p) {
    uint2 v;
    asm volatile("ld.global.cg.v2.u32 {%0,%1},[%2];\n" : "=r"(v.x), "=r"(v.y) : "l"(p));
    return v;
}

__device__ __forceinline__ float fast_sigmoid(float x) {
    return __fdividef(1.f, 1.f + __expf(-x));
}
__device__ __forceinline__ float fast_tanh(float x) {
    return 1.f - __fdividef(2.f, __expf(2.f * x) + 1.f);
}

// ---------------- prep kernels ---------------------------------------------
// [N][K] fp32 -> transposed [K][N=2048] fp16 (for xg GEMM's Wih)
__global__ void conv_wih_h_kernel(const float* __restrict__ src,
                                  __half* __restrict__ dst) {
    int idx = blockIdx.x * 256 + threadIdx.x;
    if (idx >= Gg * Ii) return;
    int n = idx / Ii, k = idx - n * Ii;
    dst[(size_t)k * Gg + n] = __float2half(src[idx]);
}

// elementwise fp32 -> fp16
__global__ void conv_h_kernel(const float* __restrict__ src, __half* __restrict__ dst, int n) {
    int idx = blockIdx.x * 256 + threadIdx.x;
    if (idx < n) dst[idx] = __float2half(src[idx]);
}

__global__ void init_kernel(__half* ha, __half* hb) {
    int i = blockIdx.x * 256 + threadIdx.x;
    if (i < 4) g_bar[i] = 0u;
    if (i < Bsz * Hh) {
        ha[i] = __float2half(0.f);
        hb[i] = __float2half(0.f);
    }
}

// ---------------- xg GEMM: C = x @ Wih^T + bih + bhh (fp16, fused x conv) ---
__global__ void __launch_bounds__(256) xg_gemm_kernel(
    const float* __restrict__ X,        // [B*T][256] fp32 (converted on load)
    const __half* __restrict__ Bw,      // [256][2048] fp16 (transposed Wih)
    const float* __restrict__ bih, const float* __restrict__ bhh,
    float* __restrict__ C)
{
    __shared__ __align__(16) __half sA[128][40];
    __shared__ __align__(16) __half sB[32][136];
    const int tid = threadIdx.x;
    const int l = tid & 31, w = tid >> 5;
    const int wm = w >> 1, wn = w & 1;
    const int n0 = blockIdx.x * 128;
    const int m0 = blockIdx.y * 128;

    float acc[2][8][4];
#pragma unroll
    for (int mi = 0; mi < 2; mi++)
#pragma unroll
        for (int nt = 0; nt < 8; nt++)
#pragma unroll
            for (int q = 0; q < 4; q++) acc[mi][nt][q] = 0.f;

    for (int k0 = 0; k0 < Ii; k0 += 32) {
        for (int s = tid; s < 512; s += 256) {
            int row = s >> 2, ch = (s & 3) * 8;
            const float* xp = X + (size_t)(m0 + row) * Ii + k0 + ch;
            float4 v0 = *(const float4*)xp;
            float4 v1 = *(const float4*)(xp + 4);
            __half hv[8];
            hv[0] = __float2half(v0.x); hv[1] = __float2half(v0.y);
            hv[2] = __float2half(v0.z); hv[3] = __float2half(v0.w);
            hv[4] = __float2half(v1.x); hv[5] = __float2half(v1.y);
            hv[6] = __float2half(v1.z); hv[7] = __float2half(v1.w);
            *(uint4*)&sA[row][ch] = *(uint4*)hv;
        }
        for (int s = tid; s < 512; s += 256) {
            int kr = s >> 4, ch = (s & 15) * 8;
            *(uint4*)&sB[kr][ch] = *(const uint4*)(Bw + (size_t)(k0 + kr) * Gg + n0 + ch);
        }
        __syncthreads();
#pragma unroll
        for (int kk = 0; kk < 32; kk += 16) {
            uint32_t af[2][4];
#pragma unroll
            for (int mi = 0; mi < 2; mi++) {
                uint32_t addr = smem_u32(
                    &sA[wm * 32 + mi * 16 + (l & 15)][kk + (l >> 4) * 8]);
                ldsm4(af[mi], addr);
            }
            uint32_t bfr[8][2];
            const int krow = (l & 15);
            const int csel = (l >> 4) * 8;
#pragma unroll
            for (int jp = 0; jp < 4; jp++) {
                uint32_t addr = smem_u32(&sB[kk + krow][wn * 64 + jp * 16 + csel]);
                uint32_t r0, r1, r2, r3;
                ldsm4t(r0, r1, r2, r3, addr);
                bfr[jp * 2][0] = r0; bfr[jp * 2][1] = r1;
                bfr[jp * 2 + 1][0] = r2; bfr[jp * 2 + 1][1] = r3;
            }
#pragma unroll
            for (int mi = 0; mi < 2; mi++)
#pragma unroll
                for (int nt = 0; nt < 8; nt++)
                    mma_f16(acc[mi][nt], af[mi], bfr[nt]);
        }
        __syncthreads();
    }

    const int r = l >> 2, cq = (l & 3) * 2;
#pragma unroll
    for (int mi = 0; mi < 2; mi++)
#pragma unroll
        for (int nt = 0; nt < 8; nt++) {
            const int col = n0 + wn * 64 + nt * 8 + cq;
            float bs0 = bih[col] + bhh[col];
            float bs1 = bih[col + 1] + bhh[col + 1];
#pragma unroll
            for (int rr = 0; rr < 2; rr++) {
                int m = m0 + wm * 32 + mi * 16 + r + rr * 8;
                float2 v = make_float2(acc[mi][nt][rr * 2 + 0] + bs0,
                                       acc[mi][nt][rr * 2 + 1] + bs1);
                *(float2*)(C + (size_t)m * Gg + col) = v;
            }
        }
}

// ---------------- persistent FP16 scan, A direct-to-register ----------------
// 128 CTAs = 4 batch tiles (128) x 32 ncol tiles (64 = 4 gates x 16 hcols).
// Barrier is PER BATCH TILE: CTA (bt,ct) only needs h rows of its own bt,
// produced by the 32 CTAs sharing bt -> 4 independent 32-CTA barriers.
#define SCAN_SMEM (512 * 72 * 2)   // 73728 B: resident B only

__global__ void __launch_bounds__(256, 1) scan_f16r_kernel(
    const __half* __restrict__ whh,
    __half* __restrict__ hA, __half* __restrict__ hB,
    const float* __restrict__ xg, __half* __restrict__ hs)
{
    extern __shared__ __align__(128) char sm[];
    const uint32_t smb = smem_u32(sm);
    const int tid = threadIdx.x, l = tid & 31, w = tid >> 5;
    const int bt = blockIdx.x >> 5;       // batch tile 0..3
    const int ctile = blockIdx.x & 31;    // ncol tile 0..31
    const int mb = bt * 128;
    const int hc0 = ctile * 16;

    // ---- fill resident B with per-16-block k-row permutation ----
    {
        __half* sB = (__half*)sm;
        for (int s = tid; s < 64 * 512; s += 256) {
            int n = s >> 9;                // 0..63 (gate*16 + hc)
            int g = s & 511;               // global k
            int gate = n >> 4, hc = n & 15;
            int q = (g & 15) >> 2;
            int r2 = g & 3;
            int f = (g & ~15) + 2 * q + (g & 1) + ((r2 >= 2) ? 8 : 0);
            sB[f * 72 + n] = whh[(size_t)(gate * Hh + hc0 + hc) * Hh + g];
        }
    }
    __syncthreads();

    // per-lane constants
    const int rowA = mb + w * 16 + (l >> 2);
    const size_t offA  = (size_t)rowA * Hh + (l & 3) * 4;   // element offset
    const size_t offA8 = offA + (size_t)8 * Hh;
    const uint32_t bcol = (uint32_t)((l >> 4) * 8) * 2;     // byte col offset
    const uint32_t brow_lane = (uint32_t)(l & 15);

    float c_reg[8];
#pragma unroll
    for (int q = 0; q < 8; q++) c_reg[q] = 0.f;

    const int a_ep = (l & 3) * 2;
    const int r0_ep = rowA;

    for (int t = 0; t < Tt; t++) {
        const __half* rh = (t & 1) ? hB : hA;
        __half* wh = (t & 1) ? hA : hB;

        // ---- issue chunk-0 A loads, then xg prefetch (latency hides under K loop)
        uint2 areg[2][16];
#pragma unroll
        for (int j = 0; j < 8; j++) {
            areg[0][j * 2]     = ldcg2(rh + offA  + j * 16);
            areg[0][j * 2 + 1] = ldcg2(rh + offA8 + j * 16);
        }
        float2 xv[16];
        {
            const float* xb  = xg + ((size_t)r0_ep * Tt + t) * Gg + hc0;
            const float* xb8 = xg + ((size_t)(r0_ep + 8) * Tt + t) * Gg + hc0;
#pragma unroll
            for (int g = 0; g < 4; g++) {
                xv[g * 2]         = *(const float2*)(xb  + g * Hh + a_ep);
                xv[g * 2 + 1]     = *(const float2*)(xb  + g * Hh + a_ep + 8);
                xv[8 + g * 2]     = *(const float2*)(xb8 + g * Hh + a_ep);
                xv[8 + g * 2 + 1] = *(const float2*)(xb8 + g * Hh + a_ep + 8);
            }
        }

        float acc[8][4];
#pragma unroll
        for (int nf = 0; nf < 8; nf++)
#pragma unroll
            for (int q = 0; q < 4; q++) acc[nf][q] = 0.f;

        // ---- 4 K-chunks of 128, register double-buffered, NO syncs ----
#pragma unroll
        for (int c = 0; c < 4; c++) {
            const int buf = c & 1;
            if (c < 3) {
                const int nxt = buf ^ 1;
                const size_t ko = (size_t)(c + 1) * 128;
#pragma unroll
                for (int j = 0; j < 8; j++) {
                    areg[nxt][j * 2]     = ldcg2(rh + offA  + ko + j * 16);
                    areg[nxt][j * 2 + 1] = ldcg2(rh + offA8 + ko + j * 16);
                }
            }
#pragma unroll
            for (int j = 0; j < 8; j++) {
                const uint32_t brow = (uint32_t)((c * 128 + j * 16 + brow_lane) * 72) * 2 + bcol;
                uint32_t bfr[8][2];
#pragma unroll
                for (int jp = 0; jp < 4; jp++) {
                    uint32_t r0, r1, r2, r3;
                    ldsm4t(r0, r1, r2, r3, smb + brow + jp * 32);
                    bfr[jp * 2][0] = r0; bfr[jp * 2][1] = r1;
                    bfr[jp * 2 + 1][0] = r2; bfr[jp * 2 + 1][1] = r3;
                }
                uint32_t a[4];
                a[0] = areg[buf][j * 2].x;
                a[1] = areg[buf][j * 2 + 1].x;
                a[2] = areg[buf][j * 2].y;
                a[3] = areg[buf][j * 2 + 1].y;
#pragma unroll
                for (int nf = 0; nf < 8; nf++)
                    mma_f16(acc[nf], a, bfr[nf]);
            }
        }

        // ---- gate epilogue (c in regs) ----
#pragma unroll
        for (int rr = 0; rr < 2; rr++) {
            const int b = r0_ep + rr * 8;
            float pre[4][4];
#pragma unroll
            for (int g = 0; g < 4; g++) {
                pre[g][0] = acc[g * 2][rr * 2]         + xv[rr * 8 + g * 2].x;
                pre[g][1] = acc[g * 2][rr * 2 + 1]     + xv[rr * 8 + g * 2].y;
                pre[g][2] = acc[g * 2 + 1][rr * 2]     + xv[rr * 8 + g * 2 + 1].x;
                pre[g][3] = acc[g * 2 + 1][rr * 2 + 1] + xv[rr * 8 + g * 2 + 1].y;
            }
            float hn[4];
#pragma unroll
            for (int s = 0; s < 4; s++) {
                float ig = fast_sigmoid(pre[0][s]);
                float fg = fast_sigmoid(pre[1][s]);
                float gg = fast_tanh(pre[2][s]);
                float og = fast_sigmoid(pre[3][s]);
                float cv = fg * c_reg[rr * 4 + s] + ig * gg;
                c_reg[rr * 4 + s] = cv;
                hn[s] = og * fast_tanh(cv);
            }
            __half2 p01, p23;
            p01.x = __float2half(hn[0]); p01.y = __float2half(hn[1]);
            p23.x = __float2half(hn[2]); p23.y = __float2half(hn[3]);
            // hs (fp16) for the head
            __half* hrow = hs + ((size_t)b * Tt + t) * Hh + hc0;
            *(__half2*)(hrow + a_ep)     = p01;
            *(__half2*)(hrow + a_ep + 8) = p23;
            // h for the recurrence
            *(__half2*)(wh + (size_t)b * Hh + hc0 + a_ep)     = p01;
            *(__half2*)(wh + (size_t)b * Hh + hc0 + a_ep + 8) = p23;
        }

        // ---- per-batch-tile barrier (32 CTAs sharing bt) ----
        if (t < Tt - 1) {
            __syncthreads();
            if (tid == 0) {
                __threadfence();
                atomicAdd(&g_bar[bt], 1u);
                const unsigned target = 32u * (unsigned)(t + 1);
                unsigned v;
                do {
                    asm volatile("ld.acquire.gpu.u32 %0,[%1];" : "=r"(v) : "l"(&g_bar[bt]));
                } while (v < target);
            }
            __syncthreads();
        }
    }
}

// ---------------- fused head: fc1 + BN1 + leaky + fc2 + BN2 + relu ---------
#define HEAD_DYN_SMEM ((512 * 32 + 512 * 33) * sizeof(float))

__global__ void __launch_bounds__(256) head_kernel(
    const float* __restrict__ fc1_w, const float* __restrict__ fc1_b,
    const float* __restrict__ fc2_w, const float* __restrict__ fc2_b,
    const float* __restrict__ bn1_g, const float* __restrict__ bn1_b,
    const float* __restrict__ bn2_g, const float* __restrict__ bn2_b,
    float* __restrict__ out)
{
    extern __shared__ float smf[];
    float* fc1t = smf;             // [512][32]
    float* sa   = smf + 512 * 32;  // [512][33]

    __shared__ float red1[8], red2[8];
    __shared__ float zbuf[Bsz];
    __shared__ float fc2s[32];
    __shared__ float stats[4];

    const int t = blockIdx.x;
    const int tid = threadIdx.x;
    const int warp = tid >> 5, lane = tid & 31;

    if (tid < 32) fc2s[tid] = fc2_w[tid];
    for (int idx = tid; idx < 32 * 512; idx += 256) {
        int o = idx >> 9, k = idx & 511;
        fc1t[k * 32 + o] = fc1_w[idx];
    }
    __syncthreads();

    const float bias_o = fc1_b[lane];
    for (int pr = 0; pr < 32; pr++) {
        const int b0 = warp * 64 + pr * 2;
        const int b1 = b0 + 1;
        const uint4* r0 = (const uint4*)(g_hs + ((size_t)b0 * Tt + t) * Hh);
        const uint4* r1 = (const uint4*)(g_hs + ((size_t)b1 * Tt + t) * Hh);
        float a0 = bias_o, a1 = bias_o;
#pragma unroll 2
        for (int k8 = 0; k8 < Hh / 8; k8++) {
            uint4 u0 = r0[k8], u1 = r1[k8];
            const __half2* h0 = (const __half2*)&u0;
            const __half2* h1 = (const __half2*)&u1;
            const float* fp = fc1t + (k8 * 8) * 32 + lane;
#pragma unroll
            for (int e = 0; e < 4; e++) {
                float2 f0 = __half22float2(h0[e]);
                float2 f1 = __half22float2(h1[e]);
                float w0 = fp[(e * 2) * 32];
                float w1 = fp[(e * 2 + 1) * 32];
                a0 += f0.x * w0 + f0.y * w1;
                a1 += f1.x * w0 + f1.y * w1;
            }
        }
        sa[b0 * 33 + lane] = a0;
        sa[b1 * 33 + lane] = a1;
    }
    __syncthreads();

    float s = 0.f, ss = 0.f;
    for (int idx = tid; idx < Bsz * 32; idx += 256) {
        float v = sa[(idx >> 5) * 33 + (idx & 31)];
        s += v; ss += v * v;
    }
#pragma unroll
    for (int off = 16; off; off >>= 1) {
        s  += __shfl_down_sync(0xffffffffu, s,  off);
        ss += __shfl_down_sync(0xffffffffu, ss, off);
    }
    if (lane == 0) { red1[warp] = s; red2[warp] = ss; }
    __syncthreads();
    if (tid == 0) {
        float S = 0.f, SS = 0.f;
        for (int wv = 0; wv < 8; wv++) { S += red1[wv]; SS += red2[wv]; }
        float m = S / 16384.f;
        float v = SS / 16384.f - m * m;
        stats[0] = m;
        stats[1] = rsqrtf(v + 1e-5f);
    }
    __syncthreads();

    const float m1 = stats[0], inv1 = stats[1];
    const float g1 = bn1_g[t], be1 = bn1_b[t];
    const float f2b = fc2_b[0];

    for (int b = tid; b < Bsz; b += 256) {
        float acc = f2b;
#pragma unroll
        for (int o = 0; o < 32; o++) {
            float a = (sa[b * 33 + o] - m1) * inv1 * g1 + be1;
            a = a > 0.f ? a : 0.1f * a;
            acc += a * fc2s[o];
        }
        zbuf[b] = acc;
    }
    __syncthreads();

    float s2 = 0.f, ss2 = 0.f;
    for (int b = tid; b < Bsz; b += 256) { float v = zbuf[b]; s2 += v; ss2 += v * v; }
#pragma unroll
    for (int off = 16; off; off >>= 1) {
        s2  += __shfl_down_sync(0xffffffffu, s2,  off);
        ss2 += __shfl_down_sync(0xffffffffu, ss2, off);
    }
    if (lane == 0) { red1[warp] = s2; red2[warp] = ss2; }
    __syncthreads();
    if (tid == 0) {
        float S = 0.f, SS = 0.f;
        for (int wv = 0; wv < 8; wv++) { S += red1[wv]; SS += red2[wv]; }
        float m = S / (float)Bsz;
        float v = SS / (float)Bsz - m * m;
        stats[2] = m;
        stats[3] = rsqrtf(v + 1e-5f);
    }
    __syncthreads();

    const float m2 = stats[2], inv2 = stats[3];
    const float g2 = bn2_g[t], be2 = bn2_b[t];
    for (int b = tid; b < Bsz; b += 256) {
        float v = (zbuf[b] - m2) * inv2 * g2 + be2;
        out[(size_t)b * Tt + t] = v > 0.f ? v : 0.f;
    }
}

// ---------------- launch ----------------------------------------------------
extern "C" void kernel_launch(void* const* d_in, const int* in_sizes, int n_in,
                              void* d_out, int out_size)
{
    const float* x     = (const float*)d_in[0];
    const float* Wih   = (const float*)d_in[1];
    const float* Whh   = (const float*)d_in[2];
    const float* bih   = (const float*)d_in[3];
    const float* bhh   = (const float*)d_in[4];
    const float* fc1_w = (const float*)d_in[5];
    const float* fc1_b = (const float*)d_in[6];
    const float* fc2_w = (const float*)d_in[7];
    const float* fc2_b = (const float*)d_in[8];
    const float* bn1_g = (const float*)d_in[9];
    const float* bn1_b = (const float*)d_in[10];
    const float* bn2_g = (const float*)d_in[11];
    const float* bn2_b = (const float*)d_in[12];
    float* out = (float*)d_out;

    cudaFuncSetAttribute(head_kernel, cudaFuncAttributeMaxDynamicSharedMemorySize,
                         (int)HEAD_DYN_SMEM);
    cudaFuncSetAttribute(scan_f16r_kernel, cudaFuncAttributeMaxDynamicSharedMemorySize,
                         SCAN_SMEM);

    float* d_xg;
    __half *d_hs, *d_wih, *d_whh, *d_hA, *d_hB;
    cudaGetSymbolAddress((void**)&d_xg,  g_xg);
    cudaGetSymbolAddress((void**)&d_hs,  g_hs);
    cudaGetSymbolAddress((void**)&d_wih, g_wih_h);
    cudaGetSymbolAddress((void**)&d_whh, g_whh_h);
    cudaGetSymbolAddress((void**)&d_hA,  g_hA);
    cudaGetSymbolAddress((void**)&d_hB,  g_hB);

    // prep
    conv_wih_h_kernel<<<(Gg * Ii + 255) / 256, 256>>>(Wih, d_wih);
    conv_h_kernel<<<(Gg * Hh + 255) / 256, 256>>>(Whh, d_whh, Gg * Hh);
    init_kernel<<<(Bsz * Hh + 255) / 256, 256>>>(d_hA, d_hB);

    // xg = x @ Wih^T + bih + bhh (fp16, x converted on load)
    xg_gemm_kernel<<<dim3(Gg / 128, (Bsz * Tt) / 128), 256>>>(
        x, d_wih, bih, bhh, d_xg);

    // persistent FP16 scan, A direct-to-register, per-bt barriers
    scan_f16r_kernel<<<NCTA, 256, SCAN_SMEM>>>(d_whh, d_hA, d_hB, d_xg, d_hs);

    // fused head (reads fp16 hs)
    head_kernel<<<Tt, 256, HEAD_DYN_SMEM>>>(fc1_w, fc1_b, fc2_w, fc2_b,
                                            bn1_g, bn1_b, bn2_g, bn2_b, out);
}